// round 4
// baseline (speedup 1.0000x reference)
#include <cuda_runtime.h>
#include <cuda_bf16.h>
#include <math.h>
#include <stdint.h>

#define NROWS 32768
#define HD    1024

// ---------------------------------------------------------------------------
// Scratch (device globals; no allocations allowed)
// ---------------------------------------------------------------------------
__device__ __nv_bfloat16 g_ahi[(size_t)NROWS * HD];
__device__ __nv_bfloat16 g_alo[(size_t)NROWS * HD];
__device__ __nv_bfloat16 g_bhi[(size_t)NROWS * HD];
__device__ __nv_bfloat16 g_blo[(size_t)NROWS * HD];
__device__ __nv_bfloat16 g_wthi[4][(size_t)HD * HD];
__device__ __nv_bfloat16 g_wtlo[2][(size_t)HD * HD];   // lo only needed for W1, W2
__device__ float g_rowsum[HD];
__device__ float g_rowsq[HD];

// ---------------------------------------------------------------------------
// PTX helpers (sm_80-era instructions only — harness PTX stage is compute_103)
// ---------------------------------------------------------------------------
__device__ __forceinline__ uint32_t smem_to_u32(const void* p) {
    uint32_t a;
    asm("{ .reg .u64 t; cvta.to.shared.u64 t, %1; cvt.u32.u64 %0, t; }" : "=r"(a) : "l"(p));
    return a;
}
#define CP_ASYNC16(dst, src) \
    asm volatile("cp.async.cg.shared.global [%0], [%1], 16;" :: "r"(dst), "l"(src))
#define CP_COMMIT() asm volatile("cp.async.commit_group;" ::: "memory")
#define CP_WAIT1()  asm volatile("cp.async.wait_group 1;" ::: "memory")
#define CP_WAIT0()  asm volatile("cp.async.wait_group 0;" ::: "memory")

#define LDSM4(r0, r1, r2, r3, addr) \
    asm volatile("ldmatrix.sync.aligned.m8n8.x4.shared.b16 {%0,%1,%2,%3}, [%4];" \
        : "=r"(r0), "=r"(r1), "=r"(r2), "=r"(r3) : "r"(addr))

#define MMA16816(d, a, b) \
    asm volatile("mma.sync.aligned.m16n8k16.row.col.f32.bf16.bf16.f32 " \
        "{%0,%1,%2,%3}, {%4,%5,%6,%7}, {%8,%9}, {%0,%1,%2,%3};" \
        : "+f"((d)[0]), "+f"((d)[1]), "+f"((d)[2]), "+f"((d)[3]) \
        : "r"((a)[0]), "r"((a)[1]), "r"((a)[2]), "r"((a)[3]), \
          "r"((b)[0]), "r"((b)[1]))

__device__ __forceinline__ void split1(float v, __nv_bfloat16& h, __nv_bfloat16& l) {
    h = __float2bfloat16(v);
    l = __float2bfloat16(v - __bfloat162float(h));
}

// ---------------------------------------------------------------------------
// Prep kernels
// ---------------------------------------------------------------------------
__global__ __launch_bounds__(256)
void split_act(const float4* __restrict__ x, __nv_bfloat162* __restrict__ hi,
               __nv_bfloat162* __restrict__ lo)
{
    size_t i = (size_t)blockIdx.x * 256 + threadIdx.x;
    float4 v = x[i];
    __nv_bfloat16 h0,l0,h1,l1,h2,l2,h3,l3;
    split1(v.x,h0,l0); split1(v.y,h1,l1); split1(v.z,h2,l2); split1(v.w,h3,l3);
    __nv_bfloat162 a,b;
    a.x=h0; a.y=h1; b.x=h2; b.y=h3;
    hi[2*i]=a; hi[2*i+1]=b;
    a.x=l0; a.y=l1; b.x=l2; b.y=l3;
    lo[2*i]=a; lo[2*i+1]=b;
}

// transpose+split weights: W[K,N] fp32 -> Wt[N,K] bf16 hi/lo
__global__ __launch_bounds__(1024)
void wsplit_t(const float* __restrict__ W, __nv_bfloat16* __restrict__ hi,
              __nv_bfloat16* __restrict__ lo)
{
    __shared__ float s[32][33];
    int n0 = blockIdx.x * 32, k0 = blockIdx.y * 32;
    s[threadIdx.y][threadIdx.x] = W[(size_t)(k0 + threadIdx.y) * HD + n0 + threadIdx.x];
    __syncthreads();
    float v = s[threadIdx.x][threadIdx.y];
    int n = n0 + threadIdx.y, k = k0 + threadIdx.x;
    __nv_bfloat16 h, l; split1(v, h, l);
    hi[(size_t)n * HD + k] = h;
    lo[(size_t)n * HD + k] = l;
}

// transpose weights hi only: W[K,N] fp32 -> Wt[N,K] bf16
__global__ __launch_bounds__(1024)
void wt_hi(const float* __restrict__ W, __nv_bfloat16* __restrict__ hi)
{
    __shared__ float s[32][33];
    int n0 = blockIdx.x * 32, k0 = blockIdx.y * 32;
    s[threadIdx.y][threadIdx.x] = W[(size_t)(k0 + threadIdx.y) * HD + n0 + threadIdx.x];
    __syncthreads();
    float v = s[threadIdx.x][threadIdx.y];
    int n = n0 + threadIdx.y, k = k0 + threadIdx.x;
    hi[(size_t)n * HD + k] = __float2bfloat16(v);
}

__global__ __launch_bounds__(256)
void cb_stats_kernel(const float* __restrict__ cb, float* __restrict__ rowsum,
                     float* __restrict__ rowsq)
{
    const int i = blockIdx.x, tid = threadIdx.x;
    const float* row = cb + (size_t)i * HD;
    float s = 0.f, q = 0.f;
    for (int j = tid; j < HD; j += 256) { float v = row[j]; s += v; q = fmaf(v, v, q); }
    __shared__ float ss[256], qq[256];
    ss[tid] = s; qq[tid] = q;
    __syncthreads();
    for (int off = 128; off > 0; off >>= 1) {
        if (tid < off) { ss[tid] += ss[tid+off]; qq[tid] += qq[tid+off]; }
        __syncthreads();
    }
    if (tid == 0) { rowsum[i] = ss[0]; rowsq[i] = qq[0]; }
}

// ---------------------------------------------------------------------------
// VQ: argmin + gather (fp32 out + plain bf16 for decoder GEMM)
// ---------------------------------------------------------------------------
__global__ __launch_bounds__(256)
void vq_kernel(const float* __restrict__ ze, const float* __restrict__ cb,
               const float* __restrict__ rowsum, const float* __restrict__ rowsq,
               float* __restrict__ zq, __nv_bfloat16* __restrict__ zqh)
{
    const int n = blockIdx.x, tid = threadIdx.x;
    const float* z = ze + (size_t)n * HD;
    float best = INFINITY; int bidx = 0x7fffffff;
    #pragma unroll
    for (int j = 0; j < 4; j++) {
        int i = tid + j * 256;
        float zv = z[i];
        float d = fmaf(1024.0f * zv, zv, fmaf(-2.0f * zv, rowsum[i], rowsq[i]));
        if (d < best || (d == best && i < bidx)) { best = d; bidx = i; }
    }
    __shared__ float sd[256]; __shared__ int si[256];
    sd[tid] = best; si[tid] = bidx;
    __syncthreads();
    for (int off = 128; off > 0; off >>= 1) {
        if (tid < off) {
            float d2 = sd[tid+off]; int i2 = si[tid+off];
            if (d2 < sd[tid] || (d2 == sd[tid] && i2 < si[tid])) { sd[tid]=d2; si[tid]=i2; }
        }
        __syncthreads();
    }
    const int idx = si[0];
    float4 v = reinterpret_cast<const float4*>(cb + (size_t)idx * HD)[tid];
    reinterpret_cast<float4*>(zq + (size_t)n * HD)[tid] = v;
    __nv_bfloat162 a, b;
    a.x = __float2bfloat16(v.x); a.y = __float2bfloat16(v.y);
    b.x = __float2bfloat16(v.z); b.y = __float2bfloat16(v.w);
    __nv_bfloat162* ph = reinterpret_cast<__nv_bfloat162*>(zqh + (size_t)n * HD);
    ph[2*tid] = a; ph[2*tid+1] = b;
}

// ---------------------------------------------------------------------------
// Common GEMM geometry: CTA tile 256x128, 512 threads, 16 warps (64x32 tiles),
// KC=64, double-buffered cp.async, 128B-row xor swizzle.
// ---------------------------------------------------------------------------
#define BM 256
#define BN 128
#define KC 64
#define NKI (HD / KC)      // 16
#define THREADS 512

// ===== 3-term kernel (encoder): C = Ahi*Bhi + Ahi*Blo + Alo*Bhi =====
#define AHI_OFF 0
#define ALO_OFF 32768
#define BHI_OFF 65536
#define BLO_OFF 81920
#define STAGE_B 98304
#define SMEM_TOTAL (2 * STAGE_B)   // 196608

__device__ __forceinline__ void load_stage3(
    uint32_t sdst,
    const __nv_bfloat16* __restrict__ Ahi, const __nv_bfloat16* __restrict__ Alo,
    const __nv_bfloat16* __restrict__ Bhi, const __nv_bfloat16* __restrict__ Blo,
    int mbase, int nbase, int c, int tid)
{
    const int kel = c * KC;
    #pragma unroll
    for (int i = 0; i < 4; ++i) {
        int id = tid + i * THREADS;
        int row = id >> 3, u = id & 7;
        CP_ASYNC16(sdst + AHI_OFF + row * 128 + ((u ^ (row & 7)) << 4),
                   (const char*)(Ahi + (size_t)(mbase + row) * HD + kel + u * 8));
    }
    #pragma unroll
    for (int i = 0; i < 4; ++i) {
        int id = tid + i * THREADS;
        int row = id >> 3, u = id & 7;
        CP_ASYNC16(sdst + ALO_OFF + row * 128 + ((u ^ (row & 7)) << 4),
                   (const char*)(Alo + (size_t)(mbase + row) * HD + kel + u * 8));
    }
    #pragma unroll
    for (int i = 0; i < 2; ++i) {
        int id = tid + i * THREADS;
        int row = id >> 3, u = id & 7;
        CP_ASYNC16(sdst + BHI_OFF + row * 128 + ((u ^ (row & 7)) << 4),
                   (const char*)(Bhi + (size_t)(nbase + row) * HD + kel + u * 8));
    }
    #pragma unroll
    for (int i = 0; i < 2; ++i) {
        int id = tid + i * THREADS;
        int row = id >> 3, u = id & 7;
        CP_ASYNC16(sdst + BLO_OFF + row * 128 + ((u ^ (row & 7)) << 4),
                   (const char*)(Blo + (size_t)(nbase + row) * HD + kel + u * 8));
    }
}

// MODE: 0 = fp32 C; 1 = split bf16 Chi/Clo.  EPI: 0 = relu, 1 = sigmoid.
template<int EPI, int MODE>
__global__ __launch_bounds__(THREADS, 1)
void gemm_mma3(const __nv_bfloat16* __restrict__ Ahi, const __nv_bfloat16* __restrict__ Alo,
               const __nv_bfloat16* __restrict__ Bhi, const __nv_bfloat16* __restrict__ Blo,
               const float* __restrict__ bias,
               float* __restrict__ Cf,
               __nv_bfloat16* __restrict__ Chi, __nv_bfloat16* __restrict__ Clo)
{
    extern __shared__ char smem[];
    const uint32_t sb = smem_to_u32(smem);
    const int tid  = threadIdx.x;
    const int wid  = tid >> 5;
    const int lane = tid & 31;
    const int wm = wid & 3;
    const int wn = wid >> 2;
    const int mbase = blockIdx.y * BM;
    const int nbase = blockIdx.x * BN;

    float acc[4][4][4];
    #pragma unroll
    for (int i = 0; i < 4; i++)
        #pragma unroll
        for (int j = 0; j < 4; j++)
            #pragma unroll
            for (int k = 0; k < 4; k++) acc[i][j][k] = 0.f;

    const int a_row_l = lane & 15;
    const int a_half  = lane >> 4;
    const int b_n_l   = (lane & 7) + ((lane >> 4) << 3);
    const int b_half  = (lane >> 3) & 1;

    load_stage3(sb, Ahi, Alo, Bhi, Blo, mbase, nbase, 0, tid);
    CP_COMMIT();

    for (int c = 0; c < NKI; ++c) {
        if (c + 1 < NKI) {
            load_stage3(sb + ((c + 1) & 1) * STAGE_B, Ahi, Alo, Bhi, Blo,
                        mbase, nbase, c + 1, tid);
            CP_COMMIT();
            CP_WAIT1();
        } else {
            CP_WAIT0();
        }
        __syncthreads();

        const uint32_t st = sb + (c & 1) * STAGE_B;
        #pragma unroll
        for (int ks = 0; ks < 4; ++ks) {
            uint32_t ah[4][4], bh[4][2], bl[4][2];
            #pragma unroll
            for (int i = 0; i < 4; ++i) {
                int row = wm * 64 + i * 16 + a_row_l;
                int u = ks * 2 + a_half;
                LDSM4(ah[i][0], ah[i][1], ah[i][2], ah[i][3],
                      st + AHI_OFF + row * 128 + ((u ^ (row & 7)) << 4));
            }
            #pragma unroll
            for (int jj = 0; jj < 2; ++jj) {
                int n = wn * 32 + jj * 16 + b_n_l;
                int u = ks * 2 + b_half;
                LDSM4(bh[jj*2][0], bh[jj*2][1], bh[jj*2+1][0], bh[jj*2+1][1],
                      st + BHI_OFF + n * 128 + ((u ^ (n & 7)) << 4));
            }
            #pragma unroll
            for (int i = 0; i < 4; ++i)
                #pragma unroll
                for (int j = 0; j < 4; ++j)
                    MMA16816(acc[i][j], ah[i], bh[j]);

            #pragma unroll
            for (int jj = 0; jj < 2; ++jj) {
                int n = wn * 32 + jj * 16 + b_n_l;
                int u = ks * 2 + b_half;
                LDSM4(bl[jj*2][0], bl[jj*2][1], bl[jj*2+1][0], bl[jj*2+1][1],
                      st + BLO_OFF + n * 128 + ((u ^ (n & 7)) << 4));
            }
            #pragma unroll
            for (int i = 0; i < 4; ++i)
                #pragma unroll
                for (int j = 0; j < 4; ++j)
                    MMA16816(acc[i][j], ah[i], bl[j]);

            #pragma unroll
            for (int i = 0; i < 4; ++i) {
                int row = wm * 64 + i * 16 + a_row_l;
                int u = ks * 2 + a_half;
                LDSM4(ah[i][0], ah[i][1], ah[i][2], ah[i][3],
                      st + ALO_OFF + row * 128 + ((u ^ (row & 7)) << 4));
            }
            #pragma unroll
            for (int i = 0; i < 4; ++i)
                #pragma unroll
                for (int j = 0; j < 4; ++j)
                    MMA16816(acc[i][j], ah[i], bh[j]);
        }
        __syncthreads();
    }

    #pragma unroll
    for (int j = 0; j < 4; ++j) {
        const int col = nbase + wn * 32 + j * 8 + (lane & 3) * 2;
        const float2 bj = *reinterpret_cast<const float2*>(bias + col);
        #pragma unroll
        for (int i = 0; i < 4; ++i) {
            const int r0 = mbase + wm * 64 + i * 16 + (lane >> 2);
            const int r1 = r0 + 8;
            float v0 = acc[i][j][0] + bj.x;
            float v1 = acc[i][j][1] + bj.y;
            float v2 = acc[i][j][2] + bj.x;
            float v3 = acc[i][j][3] + bj.y;
            if (EPI == 0) {
                v0 = fmaxf(v0, 0.f); v1 = fmaxf(v1, 0.f);
                v2 = fmaxf(v2, 0.f); v3 = fmaxf(v3, 0.f);
            } else {
                v0 = 1.f / (1.f + expf(-v0)); v1 = 1.f / (1.f + expf(-v1));
                v2 = 1.f / (1.f + expf(-v2)); v3 = 1.f / (1.f + expf(-v3));
            }
            if (MODE == 0) {
                float2 p0 = {v0, v1}, p1 = {v2, v3};
                *reinterpret_cast<float2*>(Cf + (size_t)r0 * HD + col) = p0;
                *reinterpret_cast<float2*>(Cf + (size_t)r1 * HD + col) = p1;
            } else {
                __nv_bfloat16 h0,l0,h1,l1,h2,l2,h3,l3;
                split1(v0,h0,l0); split1(v1,h1,l1); split1(v2,h2,l2); split1(v3,h3,l3);
                __nv_bfloat162 hh0; hh0.x=h0; hh0.y=h1;
                __nv_bfloat162 ll0; ll0.x=l0; ll0.y=l1;
                __nv_bfloat162 hh1; hh1.x=h2; hh1.y=h3;
                __nv_bfloat162 ll1; ll1.x=l2; ll1.y=l3;
                *reinterpret_cast<__nv_bfloat162*>(Chi + (size_t)r0 * HD + col) = hh0;
                *reinterpret_cast<__nv_bfloat162*>(Clo + (size_t)r0 * HD + col) = ll0;
                *reinterpret_cast<__nv_bfloat162*>(Chi + (size_t)r1 * HD + col) = hh1;
                *reinterpret_cast<__nv_bfloat162*>(Clo + (size_t)r1 * HD + col) = ll1;
            }
        }
    }
}

// ===== 1-term kernel (decoder): C = act(A*B + bias), plain bf16 =====
#define A1_OFF 0
#define B1_OFF 32768
#define STAGE1_B 49152
#define SMEM1_TOTAL (2 * STAGE1_B)   // 98304 -> 2 CTAs/SM

__device__ __forceinline__ void load_stage1(
    uint32_t sdst,
    const __nv_bfloat16* __restrict__ A, const __nv_bfloat16* __restrict__ B,
    int mbase, int nbase, int c, int tid)
{
    const int kel = c * KC;
    #pragma unroll
    for (int i = 0; i < 4; ++i) {
        int id = tid + i * THREADS;
        int row = id >> 3, u = id & 7;
        CP_ASYNC16(sdst + A1_OFF + row * 128 + ((u ^ (row & 7)) << 4),
                   (const char*)(A + (size_t)(mbase + row) * HD + kel + u * 8));
    }
    #pragma unroll
    for (int i = 0; i < 2; ++i) {
        int id = tid + i * THREADS;
        int row = id >> 3, u = id & 7;
        CP_ASYNC16(sdst + B1_OFF + row * 128 + ((u ^ (row & 7)) << 4),
                   (const char*)(B + (size_t)(nbase + row) * HD + kel + u * 8));
    }
}

// MODE: 0 = fp32 C; 1 = bf16 Chi only.
template<int EPI, int MODE>
__global__ __launch_bounds__(THREADS, 2)
void gemm_mma1(const __nv_bfloat16* __restrict__ A, const __nv_bfloat16* __restrict__ B,
               const float* __restrict__ bias,
               float* __restrict__ Cf, __nv_bfloat16* __restrict__ Chi)
{
    extern __shared__ char smem[];
    const uint32_t sb = smem_to_u32(smem);
    const int tid  = threadIdx.x;
    const int wid  = tid >> 5;
    const int lane = tid & 31;
    const int wm = wid & 3;
    const int wn = wid >> 2;
    const int mbase = blockIdx.y * BM;
    const int nbase = blockIdx.x * BN;

    float acc[4][4][4];
    #pragma unroll
    for (int i = 0; i < 4; i++)
        #pragma unroll
        for (int j = 0; j < 4; j++)
            #pragma unroll
            for (int k = 0; k < 4; k++) acc[i][j][k] = 0.f;

    const int a_row_l = lane & 15;
    const int a_half  = lane >> 4;
    const int b_n_l   = (lane & 7) + ((lane >> 4) << 3);
    const int b_half  = (lane >> 3) & 1;

    load_stage1(sb, A, B, mbase, nbase, 0, tid);
    CP_COMMIT();

    for (int c = 0; c < NKI; ++c) {
        if (c + 1 < NKI) {
            load_stage1(sb + ((c + 1) & 1) * STAGE1_B, A, B, mbase, nbase, c + 1, tid);
            CP_COMMIT();
            CP_WAIT1();
        } else {
            CP_WAIT0();
        }
        __syncthreads();

        const uint32_t st = sb + (c & 1) * STAGE1_B;
        #pragma unroll
        for (int ks = 0; ks < 4; ++ks) {
            uint32_t ah[4][4], bh[4][2];
            #pragma unroll
            for (int i = 0; i < 4; ++i) {
                int row = wm * 64 + i * 16 + a_row_l;
                int u = ks * 2 + a_half;
                LDSM4(ah[i][0], ah[i][1], ah[i][2], ah[i][3],
                      st + A1_OFF + row * 128 + ((u ^ (row & 7)) << 4));
            }
            #pragma unroll
            for (int jj = 0; jj < 2; ++jj) {
                int n = wn * 32 + jj * 16 + b_n_l;
                int u = ks * 2 + b_half;
                LDSM4(bh[jj*2][0], bh[jj*2][1], bh[jj*2+1][0], bh[jj*2+1][1],
                      st + B1_OFF + n * 128 + ((u ^ (n & 7)) << 4));
            }
            #pragma unroll
            for (int i = 0; i < 4; ++i)
                #pragma unroll
                for (int j = 0; j < 4; ++j)
                    MMA16816(acc[i][j], ah[i], bh[j]);
        }
        __syncthreads();
    }

    #pragma unroll
    for (int j = 0; j < 4; ++j) {
        const int col = nbase + wn * 32 + j * 8 + (lane & 3) * 2;
        const float2 bj = *reinterpret_cast<const float2*>(bias + col);
        #pragma unroll
        for (int i = 0; i < 4; ++i) {
            const int r0 = mbase + wm * 64 + i * 16 + (lane >> 2);
            const int r1 = r0 + 8;
            float v0 = acc[i][j][0] + bj.x;
            float v1 = acc[i][j][1] + bj.y;
            float v2 = acc[i][j][2] + bj.x;
            float v3 = acc[i][j][3] + bj.y;
            if (EPI == 0) {
                v0 = fmaxf(v0, 0.f); v1 = fmaxf(v1, 0.f);
                v2 = fmaxf(v2, 0.f); v3 = fmaxf(v3, 0.f);
            } else {
                v0 = 1.f / (1.f + expf(-v0)); v1 = 1.f / (1.f + expf(-v1));
                v2 = 1.f / (1.f + expf(-v2)); v3 = 1.f / (1.f + expf(-v3));
            }
            if (MODE == 0) {
                float2 p0 = {v0, v1}, p1 = {v2, v3};
                *reinterpret_cast<float2*>(Cf + (size_t)r0 * HD + col) = p0;
                *reinterpret_cast<float2*>(Cf + (size_t)r1 * HD + col) = p1;
            } else {
                __nv_bfloat162 hh0, hh1;
                hh0.x = __float2bfloat16(v0); hh0.y = __float2bfloat16(v1);
                hh1.x = __float2bfloat16(v2); hh1.y = __float2bfloat16(v3);
                *reinterpret_cast<__nv_bfloat162*>(Chi + (size_t)r0 * HD + col) = hh0;
                *reinterpret_cast<__nv_bfloat162*>(Chi + (size_t)r1 * HD + col) = hh1;
            }
        }
    }
}

// ---------------------------------------------------------------------------
// Launch
// ---------------------------------------------------------------------------
extern "C" void kernel_launch(void* const* d_in, const int* in_sizes, int n_in,
                              void* d_out, int out_size)
{
    const float* x  = (const float*)d_in[0];
    const float* W1 = (const float*)d_in[1];
    const float* b1 = (const float*)d_in[2];
    const float* W2 = (const float*)d_in[3];
    const float* b2 = (const float*)d_in[4];
    const float* cb = (const float*)d_in[5];
    const float* W3 = (const float*)d_in[6];
    const float* b3 = (const float*)d_in[7];
    const float* W4 = (const float*)d_in[8];
    const float* b4 = (const float*)d_in[9];

    float* out = (float*)d_out;
    float* x_recon = out;
    float* z_e = out + (size_t)NROWS * HD;
    float* z_q = z_e + (size_t)NROWS * HD;

    __nv_bfloat16 *ahi, *alo, *bhi, *blo, *wh, *wl;
    float *rs, *rq;
    cudaGetSymbolAddress((void**)&ahi, g_ahi);
    cudaGetSymbolAddress((void**)&alo, g_alo);
    cudaGetSymbolAddress((void**)&bhi, g_bhi);
    cudaGetSymbolAddress((void**)&blo, g_blo);
    cudaGetSymbolAddress((void**)&wh,  g_wthi);
    cudaGetSymbolAddress((void**)&wl,  g_wtlo);
    cudaGetSymbolAddress((void**)&rs,  g_rowsum);
    cudaGetSymbolAddress((void**)&rq,  g_rowsq);
    const size_t WSZ = (size_t)HD * HD;

    cudaFuncSetAttribute(gemm_mma3<0,1>, cudaFuncAttributeMaxDynamicSharedMemorySize, SMEM_TOTAL);
    cudaFuncSetAttribute(gemm_mma3<0,0>, cudaFuncAttributeMaxDynamicSharedMemorySize, SMEM_TOTAL);
    cudaFuncSetAttribute(gemm_mma1<0,1>, cudaFuncAttributeMaxDynamicSharedMemorySize, SMEM1_TOTAL);
    cudaFuncSetAttribute(gemm_mma1<1,0>, cudaFuncAttributeMaxDynamicSharedMemorySize, SMEM1_TOTAL);

    // ---- prep ----
    split_act<<<(NROWS * HD / 4) / 256, 256>>>((const float4*)x,
        (__nv_bfloat162*)ahi, (__nv_bfloat162*)alo);
    dim3 tb(32, 32), tg(HD / 32, HD / 32);
    wsplit_t<<<tg, tb>>>(W1, wh + 0 * WSZ, wl + 0 * WSZ);
    wsplit_t<<<tg, tb>>>(W2, wh + 1 * WSZ, wl + 1 * WSZ);
    wt_hi  <<<tg, tb>>>(W3, wh + 2 * WSZ);
    wt_hi  <<<tg, tb>>>(W4, wh + 3 * WSZ);
    cb_stats_kernel<<<HD, 256>>>(cb, rs, rq);

    dim3 gg(HD / BN, NROWS / BM);   // (8, 128)
    dim3 blk(THREADS);

    // encoder (3-term, high accuracy for VQ argmin)
    gemm_mma3<0,1><<<gg, blk, SMEM_TOTAL>>>(ahi, alo, wh + 0*WSZ, wl + 0*WSZ, b1,
                                            nullptr, bhi, blo);          // h1 (split)
    gemm_mma3<0,0><<<gg, blk, SMEM_TOTAL>>>(bhi, blo, wh + 1*WSZ, wl + 1*WSZ, b2,
                                            z_e, nullptr, nullptr);      // z_e fp32

    // VQ (writes z_q fp32 + bf16 into ahi)
    vq_kernel<<<NROWS, 256>>>(z_e, cb, rs, rq, z_q, ahi);

    // decoder (1-term bf16 — error diluted through sigmoid, within 1e-3 gate)
    gemm_mma1<0,1><<<gg, blk, SMEM1_TOTAL>>>(ahi, wh + 2*WSZ, b3,
                                             nullptr, bhi);              // h3 bf16
    gemm_mma1<1,0><<<gg, blk, SMEM1_TOTAL>>>(bhi, wh + 3*WSZ, b4,
                                             x_recon, nullptr);          // x_recon fp32
}

// round 5
// speedup vs baseline: 1.6751x; 1.6751x over previous
#include <cuda_runtime.h>
#include <cuda_bf16.h>
#include <math.h>
#include <stdint.h>

#define NROWS 32768
#define HD    1024

// ---------------------------------------------------------------------------
// Scratch (device globals; no allocations allowed)
// ---------------------------------------------------------------------------
__device__ __nv_bfloat16 g_ahi[(size_t)NROWS * HD];
__device__ __nv_bfloat16 g_alo[(size_t)NROWS * HD];
__device__ __nv_bfloat16 g_bhi[(size_t)NROWS * HD];
__device__ __nv_bfloat16 g_blo[(size_t)NROWS * HD];
__device__ __nv_bfloat16 g_wthi[4][(size_t)HD * HD];
__device__ __nv_bfloat16 g_wtlo[2][(size_t)HD * HD];   // lo only needed for W1, W2
__device__ float g_rowsum[HD];
__device__ float g_rowsq[HD];

// ---------------------------------------------------------------------------
// PTX helpers (sm_80-era instructions only — harness PTX stage is compute_103)
// ---------------------------------------------------------------------------
__device__ __forceinline__ uint32_t smem_to_u32(const void* p) {
    uint32_t a;
    asm("{ .reg .u64 t; cvta.to.shared.u64 t, %1; cvt.u32.u64 %0, t; }" : "=r"(a) : "l"(p));
    return a;
}
#define CP_ASYNC16(dst, src) \
    asm volatile("cp.async.cg.shared.global [%0], [%1], 16;" :: "r"(dst), "l"(src))
#define CP_COMMIT() asm volatile("cp.async.commit_group;" ::: "memory")
#define CP_WAIT2()  asm volatile("cp.async.wait_group 2;" ::: "memory")
#define CP_WAIT1()  asm volatile("cp.async.wait_group 1;" ::: "memory")
#define CP_WAIT0()  asm volatile("cp.async.wait_group 0;" ::: "memory")

#define LDSM4(r0, r1, r2, r3, addr) \
    asm volatile("ldmatrix.sync.aligned.m8n8.x4.shared.b16 {%0,%1,%2,%3}, [%4];" \
        : "=r"(r0), "=r"(r1), "=r"(r2), "=r"(r3) : "r"(addr))

#define MMA16816(d, a, b) \
    asm volatile("mma.sync.aligned.m16n8k16.row.col.f32.bf16.bf16.f32 " \
        "{%0,%1,%2,%3}, {%4,%5,%6,%7}, {%8,%9}, {%0,%1,%2,%3};" \
        : "+f"((d)[0]), "+f"((d)[1]), "+f"((d)[2]), "+f"((d)[3]) \
        : "r"((a)[0]), "r"((a)[1]), "r"((a)[2]), "r"((a)[3]), \
          "r"((b)[0]), "r"((b)[1]))

__device__ __forceinline__ void split1(float v, __nv_bfloat16& h, __nv_bfloat16& l) {
    h = __float2bfloat16(v);
    l = __float2bfloat16(v - __bfloat162float(h));
}

// ---------------------------------------------------------------------------
// Prep kernels
// ---------------------------------------------------------------------------
__global__ __launch_bounds__(256)
void split_act(const float4* __restrict__ x, __nv_bfloat162* __restrict__ hi,
               __nv_bfloat162* __restrict__ lo)
{
    size_t i = (size_t)blockIdx.x * 256 + threadIdx.x;
    float4 v = x[i];
    __nv_bfloat16 h0,l0,h1,l1,h2,l2,h3,l3;
    split1(v.x,h0,l0); split1(v.y,h1,l1); split1(v.z,h2,l2); split1(v.w,h3,l3);
    __nv_bfloat162 a,b;
    a.x=h0; a.y=h1; b.x=h2; b.y=h3;
    hi[2*i]=a; hi[2*i+1]=b;
    a.x=l0; a.y=l1; b.x=l2; b.y=l3;
    lo[2*i]=a; lo[2*i+1]=b;
}

// transpose+split weights: W[K,N] fp32 -> Wt[N,K] bf16 hi/lo
__global__ __launch_bounds__(1024)
void wsplit_t(const float* __restrict__ W, __nv_bfloat16* __restrict__ hi,
              __nv_bfloat16* __restrict__ lo)
{
    __shared__ float s[32][33];
    int n0 = blockIdx.x * 32, k0 = blockIdx.y * 32;
    s[threadIdx.y][threadIdx.x] = W[(size_t)(k0 + threadIdx.y) * HD + n0 + threadIdx.x];
    __syncthreads();
    float v = s[threadIdx.x][threadIdx.y];
    int n = n0 + threadIdx.y, k = k0 + threadIdx.x;
    __nv_bfloat16 h, l; split1(v, h, l);
    hi[(size_t)n * HD + k] = h;
    lo[(size_t)n * HD + k] = l;
}

// transpose weights hi only: W[K,N] fp32 -> Wt[N,K] bf16
__global__ __launch_bounds__(1024)
void wt_hi(const float* __restrict__ W, __nv_bfloat16* __restrict__ hi)
{
    __shared__ float s[32][33];
    int n0 = blockIdx.x * 32, k0 = blockIdx.y * 32;
    s[threadIdx.y][threadIdx.x] = W[(size_t)(k0 + threadIdx.y) * HD + n0 + threadIdx.x];
    __syncthreads();
    float v = s[threadIdx.x][threadIdx.y];
    int n = n0 + threadIdx.y, k = k0 + threadIdx.x;
    hi[(size_t)n * HD + k] = __float2bfloat16(v);
}

__global__ __launch_bounds__(256)
void cb_stats_kernel(const float* __restrict__ cb, float* __restrict__ rowsum,
                     float* __restrict__ rowsq)
{
    const int i = blockIdx.x, tid = threadIdx.x;
    const float* row = cb + (size_t)i * HD;
    float s = 0.f, q = 0.f;
    for (int j = tid; j < HD; j += 256) { float v = row[j]; s += v; q = fmaf(v, v, q); }
    __shared__ float ss[256], qq[256];
    ss[tid] = s; qq[tid] = q;
    __syncthreads();
    for (int off = 128; off > 0; off >>= 1) {
        if (tid < off) { ss[tid] += ss[tid+off]; qq[tid] += qq[tid+off]; }
        __syncthreads();
    }
    if (tid == 0) { rowsum[i] = ss[0]; rowsq[i] = qq[0]; }
}

// ---------------------------------------------------------------------------
// VQ: argmin + gather (fp32 out + plain bf16 for decoder GEMM)
// ---------------------------------------------------------------------------
__global__ __launch_bounds__(256)
void vq_kernel(const float* __restrict__ ze, const float* __restrict__ cb,
               const float* __restrict__ rowsum, const float* __restrict__ rowsq,
               float* __restrict__ zq, __nv_bfloat16* __restrict__ zqh)
{
    const int n = blockIdx.x, tid = threadIdx.x;
    const float* z = ze + (size_t)n * HD;
    float best = INFINITY; int bidx = 0x7fffffff;
    #pragma unroll
    for (int j = 0; j < 4; j++) {
        int i = tid + j * 256;
        float zv = z[i];
        float d = fmaf(1024.0f * zv, zv, fmaf(-2.0f * zv, rowsum[i], rowsq[i]));
        if (d < best || (d == best && i < bidx)) { best = d; bidx = i; }
    }
    __shared__ float sd[256]; __shared__ int si[256];
    sd[tid] = best; si[tid] = bidx;
    __syncthreads();
    for (int off = 128; off > 0; off >>= 1) {
        if (tid < off) {
            float d2 = sd[tid+off]; int i2 = si[tid+off];
            if (d2 < sd[tid] || (d2 == sd[tid] && i2 < si[tid])) { sd[tid]=d2; si[tid]=i2; }
        }
        __syncthreads();
    }
    const int idx = si[0];
    float4 v = reinterpret_cast<const float4*>(cb + (size_t)idx * HD)[tid];
    reinterpret_cast<float4*>(zq + (size_t)n * HD)[tid] = v;
    __nv_bfloat162 a, b;
    a.x = __float2bfloat16(v.x); a.y = __float2bfloat16(v.y);
    b.x = __float2bfloat16(v.z); b.y = __float2bfloat16(v.w);
    __nv_bfloat162* ph = reinterpret_cast<__nv_bfloat162*>(zqh + (size_t)n * HD);
    ph[2*tid] = a; ph[2*tid+1] = b;
}

// ---------------------------------------------------------------------------
// Common GEMM geometry: CTA tile 256x128, 512 threads, 16 warps (64x32 tiles),
// KC=64, cp.async pipeline, 128B-row xor swizzle.
// ---------------------------------------------------------------------------
#define BM 256
#define BN 128
#define KC 64
#define NKI (HD / KC)      // 16
#define THREADS 512

// ===== 3-term kernel (encoder): C = Ahi*Bhi + Ahi*Blo + Alo*Bhi =====
#define AHI_OFF 0
#define ALO_OFF 32768
#define BHI_OFF 65536
#define BLO_OFF 81920
#define STAGE_B 98304
#define SMEM_TOTAL (2 * STAGE_B)   // 196608

__device__ __forceinline__ void load_stage3(
    uint32_t sdst,
    const __nv_bfloat16* __restrict__ Ahi, const __nv_bfloat16* __restrict__ Alo,
    const __nv_bfloat16* __restrict__ Bhi, const __nv_bfloat16* __restrict__ Blo,
    int mbase, int nbase, int c, int tid)
{
    const int kel = c * KC;
    #pragma unroll
    for (int i = 0; i < 4; ++i) {
        int id = tid + i * THREADS;
        int row = id >> 3, u = id & 7;
        CP_ASYNC16(sdst + AHI_OFF + row * 128 + ((u ^ (row & 7)) << 4),
                   (const char*)(Ahi + (size_t)(mbase + row) * HD + kel + u * 8));
    }
    #pragma unroll
    for (int i = 0; i < 4; ++i) {
        int id = tid + i * THREADS;
        int row = id >> 3, u = id & 7;
        CP_ASYNC16(sdst + ALO_OFF + row * 128 + ((u ^ (row & 7)) << 4),
                   (const char*)(Alo + (size_t)(mbase + row) * HD + kel + u * 8));
    }
    #pragma unroll
    for (int i = 0; i < 2; ++i) {
        int id = tid + i * THREADS;
        int row = id >> 3, u = id & 7;
        CP_ASYNC16(sdst + BHI_OFF + row * 128 + ((u ^ (row & 7)) << 4),
                   (const char*)(Bhi + (size_t)(nbase + row) * HD + kel + u * 8));
    }
    #pragma unroll
    for (int i = 0; i < 2; ++i) {
        int id = tid + i * THREADS;
        int row = id >> 3, u = id & 7;
        CP_ASYNC16(sdst + BLO_OFF + row * 128 + ((u ^ (row & 7)) << 4),
                   (const char*)(Blo + (size_t)(nbase + row) * HD + kel + u * 8));
    }
}

// MODE: 0 = fp32 C; 1 = split bf16 Chi/Clo.  EPI: 0 = relu, 1 = sigmoid.
template<int EPI, int MODE>
__global__ __launch_bounds__(THREADS, 1)
void gemm_mma3(const __nv_bfloat16* __restrict__ Ahi, const __nv_bfloat16* __restrict__ Alo,
               const __nv_bfloat16* __restrict__ Bhi, const __nv_bfloat16* __restrict__ Blo,
               const float* __restrict__ bias,
               float* __restrict__ Cf,
               __nv_bfloat16* __restrict__ Chi, __nv_bfloat16* __restrict__ Clo)
{
    extern __shared__ char smem[];
    const uint32_t sb = smem_to_u32(smem);
    const int tid  = threadIdx.x;
    const int wid  = tid >> 5;
    const int lane = tid & 31;
    const int wm = wid & 3;
    const int wn = wid >> 2;
    const int mbase = blockIdx.y * BM;
    const int nbase = blockIdx.x * BN;

    float acc[4][4][4];
    #pragma unroll
    for (int i = 0; i < 4; i++)
        #pragma unroll
        for (int j = 0; j < 4; j++)
            #pragma unroll
            for (int k = 0; k < 4; k++) acc[i][j][k] = 0.f;

    const int a_row_l = lane & 15;
    const int a_half  = lane >> 4;
    const int b_n_l   = (lane & 7) + ((lane >> 4) << 3);
    const int b_half  = (lane >> 3) & 1;

    load_stage3(sb, Ahi, Alo, Bhi, Blo, mbase, nbase, 0, tid);
    CP_COMMIT();

    for (int c = 0; c < NKI; ++c) {
        if (c + 1 < NKI) {
            load_stage3(sb + ((c + 1) & 1) * STAGE_B, Ahi, Alo, Bhi, Blo,
                        mbase, nbase, c + 1, tid);
            CP_COMMIT();
            CP_WAIT1();
        } else {
            CP_WAIT0();
        }
        __syncthreads();

        const uint32_t st = sb + (c & 1) * STAGE_B;
        #pragma unroll
        for (int ks = 0; ks < 4; ++ks) {
            uint32_t ah[4][4], bh[4][2], bl[4][2];
            #pragma unroll
            for (int i = 0; i < 4; ++i) {
                int row = wm * 64 + i * 16 + a_row_l;
                int u = ks * 2 + a_half;
                LDSM4(ah[i][0], ah[i][1], ah[i][2], ah[i][3],
                      st + AHI_OFF + row * 128 + ((u ^ (row & 7)) << 4));
            }
            #pragma unroll
            for (int jj = 0; jj < 2; ++jj) {
                int n = wn * 32 + jj * 16 + b_n_l;
                int u = ks * 2 + b_half;
                LDSM4(bh[jj*2][0], bh[jj*2][1], bh[jj*2+1][0], bh[jj*2+1][1],
                      st + BHI_OFF + n * 128 + ((u ^ (n & 7)) << 4));
            }
            #pragma unroll
            for (int i = 0; i < 4; ++i)
                #pragma unroll
                for (int j = 0; j < 4; ++j)
                    MMA16816(acc[i][j], ah[i], bh[j]);

            #pragma unroll
            for (int jj = 0; jj < 2; ++jj) {
                int n = wn * 32 + jj * 16 + b_n_l;
                int u = ks * 2 + b_half;
                LDSM4(bl[jj*2][0], bl[jj*2][1], bl[jj*2+1][0], bl[jj*2+1][1],
                      st + BLO_OFF + n * 128 + ((u ^ (n & 7)) << 4));
            }
            #pragma unroll
            for (int i = 0; i < 4; ++i)
                #pragma unroll
                for (int j = 0; j < 4; ++j)
                    MMA16816(acc[i][j], ah[i], bl[j]);

            #pragma unroll
            for (int i = 0; i < 4; ++i) {
                int row = wm * 64 + i * 16 + a_row_l;
                int u = ks * 2 + a_half;
                LDSM4(ah[i][0], ah[i][1], ah[i][2], ah[i][3],
                      st + ALO_OFF + row * 128 + ((u ^ (row & 7)) << 4));
            }
            #pragma unroll
            for (int i = 0; i < 4; ++i)
                #pragma unroll
                for (int j = 0; j < 4; ++j)
                    MMA16816(acc[i][j], ah[i], bh[j]);
        }
        __syncthreads();
    }

    #pragma unroll
    for (int j = 0; j < 4; ++j) {
        const int col = nbase + wn * 32 + j * 8 + (lane & 3) * 2;
        const float2 bj = *reinterpret_cast<const float2*>(bias + col);
        #pragma unroll
        for (int i = 0; i < 4; ++i) {
            const int r0 = mbase + wm * 64 + i * 16 + (lane >> 2);
            const int r1 = r0 + 8;
            float v0 = acc[i][j][0] + bj.x;
            float v1 = acc[i][j][1] + bj.y;
            float v2 = acc[i][j][2] + bj.x;
            float v3 = acc[i][j][3] + bj.y;
            if (EPI == 0) {
                v0 = fmaxf(v0, 0.f); v1 = fmaxf(v1, 0.f);
                v2 = fmaxf(v2, 0.f); v3 = fmaxf(v3, 0.f);
            } else {
                v0 = 1.f / (1.f + expf(-v0)); v1 = 1.f / (1.f + expf(-v1));
                v2 = 1.f / (1.f + expf(-v2)); v3 = 1.f / (1.f + expf(-v3));
            }
            if (MODE == 0) {
                float2 p0 = {v0, v1}, p1 = {v2, v3};
                *reinterpret_cast<float2*>(Cf + (size_t)r0 * HD + col) = p0;
                *reinterpret_cast<float2*>(Cf + (size_t)r1 * HD + col) = p1;
            } else {
                __nv_bfloat16 h0,l0,h1,l1,h2,l2,h3,l3;
                split1(v0,h0,l0); split1(v1,h1,l1); split1(v2,h2,l2); split1(v3,h3,l3);
                __nv_bfloat162 hh0; hh0.x=h0; hh0.y=h1;
                __nv_bfloat162 ll0; ll0.x=l0; ll0.y=l1;
                __nv_bfloat162 hh1; hh1.x=h2; hh1.y=h3;
                __nv_bfloat162 ll1; ll1.x=l2; ll1.y=l3;
                *reinterpret_cast<__nv_bfloat162*>(Chi + (size_t)r0 * HD + col) = hh0;
                *reinterpret_cast<__nv_bfloat162*>(Clo + (size_t)r0 * HD + col) = ll0;
                *reinterpret_cast<__nv_bfloat162*>(Chi + (size_t)r1 * HD + col) = hh1;
                *reinterpret_cast<__nv_bfloat162*>(Clo + (size_t)r1 * HD + col) = ll1;
            }
        }
    }
}

// ===== 1-term kernel (decoder): C = act(A*B + bias), plain bf16 =====
// 3-stage cp.async pipeline, occupancy 1 (full registers, no spills).
#define A1_OFF 0
#define B1_OFF 32768
#define STAGE1_B 49152
#define SMEM1_TOTAL (3 * STAGE1_B)   // 147456

__device__ __forceinline__ void load_stage1(
    uint32_t sdst,
    const __nv_bfloat16* __restrict__ A, const __nv_bfloat16* __restrict__ B,
    int mbase, int nbase, int c, int tid)
{
    const int kel = c * KC;
    #pragma unroll
    for (int i = 0; i < 4; ++i) {
        int id = tid + i * THREADS;
        int row = id >> 3, u = id & 7;
        CP_ASYNC16(sdst + A1_OFF + row * 128 + ((u ^ (row & 7)) << 4),
                   (const char*)(A + (size_t)(mbase + row) * HD + kel + u * 8));
    }
    #pragma unroll
    for (int i = 0; i < 2; ++i) {
        int id = tid + i * THREADS;
        int row = id >> 3, u = id & 7;
        CP_ASYNC16(sdst + B1_OFF + row * 128 + ((u ^ (row & 7)) << 4),
                   (const char*)(B + (size_t)(nbase + row) * HD + kel + u * 8));
    }
}

// MODE: 0 = fp32 C; 1 = bf16 Chi only.
template<int EPI, int MODE>
__global__ __launch_bounds__(THREADS, 1)
void gemm_mma1(const __nv_bfloat16* __restrict__ A, const __nv_bfloat16* __restrict__ B,
               const float* __restrict__ bias,
               float* __restrict__ Cf, __nv_bfloat16* __restrict__ Chi)
{
    extern __shared__ char smem[];
    const uint32_t sb = smem_to_u32(smem);
    const int tid  = threadIdx.x;
    const int wid  = tid >> 5;
    const int lane = tid & 31;
    const int wm = wid & 3;
    const int wn = wid >> 2;
    const int mbase = blockIdx.y * BM;
    const int nbase = blockIdx.x * BN;

    float acc[4][4][4];
    #pragma unroll
    for (int i = 0; i < 4; i++)
        #pragma unroll
        for (int j = 0; j < 4; j++)
            #pragma unroll
            for (int k = 0; k < 4; k++) acc[i][j][k] = 0.f;

    const int a_row_l = lane & 15;
    const int a_half  = lane >> 4;
    const int b_n_l   = (lane & 7) + ((lane >> 4) << 3);
    const int b_half  = (lane >> 3) & 1;

    load_stage1(sb + 0 * STAGE1_B, A, B, mbase, nbase, 0, tid);
    CP_COMMIT();
    load_stage1(sb + 1 * STAGE1_B, A, B, mbase, nbase, 1, tid);
    CP_COMMIT();

    int buf = 0;
    for (int c = 0; c < NKI; ++c) {
        if (c + 2 < NKI) {
            int b2 = buf + 2; if (b2 >= 3) b2 -= 3;
            load_stage1(sb + b2 * STAGE1_B, A, B, mbase, nbase, c + 2, tid);
            CP_COMMIT();
            CP_WAIT2();
        } else if (c + 1 < NKI) {
            CP_WAIT1();
        } else {
            CP_WAIT0();
        }
        __syncthreads();

        const uint32_t st = sb + buf * STAGE1_B;
        #pragma unroll
        for (int ks = 0; ks < 4; ++ks) {
            uint32_t ah[4][4], bh[4][2];
            #pragma unroll
            for (int i = 0; i < 4; ++i) {
                int row = wm * 64 + i * 16 + a_row_l;
                int u = ks * 2 + a_half;
                LDSM4(ah[i][0], ah[i][1], ah[i][2], ah[i][3],
                      st + A1_OFF + row * 128 + ((u ^ (row & 7)) << 4));
            }
            #pragma unroll
            for (int jj = 0; jj < 2; ++jj) {
                int n = wn * 32 + jj * 16 + b_n_l;
                int u = ks * 2 + b_half;
                LDSM4(bh[jj*2][0], bh[jj*2][1], bh[jj*2+1][0], bh[jj*2+1][1],
                      st + B1_OFF + n * 128 + ((u ^ (n & 7)) << 4));
            }
            #pragma unroll
            for (int i = 0; i < 4; ++i)
                #pragma unroll
                for (int j = 0; j < 4; ++j)
                    MMA16816(acc[i][j], ah[i], bh[j]);
        }
        __syncthreads();
        buf = buf + 1; if (buf == 3) buf = 0;
    }

    #pragma unroll
    for (int j = 0; j < 4; ++j) {
        const int col = nbase + wn * 32 + j * 8 + (lane & 3) * 2;
        const float2 bj = *reinterpret_cast<const float2*>(bias + col);
        #pragma unroll
        for (int i = 0; i < 4; ++i) {
            const int r0 = mbase + wm * 64 + i * 16 + (lane >> 2);
            const int r1 = r0 + 8;
            float v0 = acc[i][j][0] + bj.x;
            float v1 = acc[i][j][1] + bj.y;
            float v2 = acc[i][j][2] + bj.x;
            float v3 = acc[i][j][3] + bj.y;
            if (EPI == 0) {
                v0 = fmaxf(v0, 0.f); v1 = fmaxf(v1, 0.f);
                v2 = fmaxf(v2, 0.f); v3 = fmaxf(v3, 0.f);
            } else {
                v0 = 1.f / (1.f + expf(-v0)); v1 = 1.f / (1.f + expf(-v1));
                v2 = 1.f / (1.f + expf(-v2)); v3 = 1.f / (1.f + expf(-v3));
            }
            if (MODE == 0) {
                float2 p0 = {v0, v1}, p1 = {v2, v3};
                *reinterpret_cast<float2*>(Cf + (size_t)r0 * HD + col) = p0;
                *reinterpret_cast<float2*>(Cf + (size_t)r1 * HD + col) = p1;
            } else {
                __nv_bfloat162 hh0, hh1;
                hh0.x = __float2bfloat16(v0); hh0.y = __float2bfloat16(v1);
                hh1.x = __float2bfloat16(v2); hh1.y = __float2bfloat16(v3);
                *reinterpret_cast<__nv_bfloat162*>(Chi + (size_t)r0 * HD + col) = hh0;
                *reinterpret_cast<__nv_bfloat162*>(Chi + (size_t)r1 * HD + col) = hh1;
            }
        }
    }
}

// ---------------------------------------------------------------------------
// Launch
// ---------------------------------------------------------------------------
extern "C" void kernel_launch(void* const* d_in, const int* in_sizes, int n_in,
                              void* d_out, int out_size)
{
    const float* x  = (const float*)d_in[0];
    const float* W1 = (const float*)d_in[1];
    const float* b1 = (const float*)d_in[2];
    const float* W2 = (const float*)d_in[3];
    const float* b2 = (const float*)d_in[4];
    const float* cb = (const float*)d_in[5];
    const float* W3 = (const float*)d_in[6];
    const float* b3 = (const float*)d_in[7];
    const float* W4 = (const float*)d_in[8];
    const float* b4 = (const float*)d_in[9];

    float* out = (float*)d_out;
    float* x_recon = out;
    float* z_e = out + (size_t)NROWS * HD;
    float* z_q = z_e + (size_t)NROWS * HD;

    __nv_bfloat16 *ahi, *alo, *bhi, *blo, *wh, *wl;
    float *rs, *rq;
    cudaGetSymbolAddress((void**)&ahi, g_ahi);
    cudaGetSymbolAddress((void**)&alo, g_alo);
    cudaGetSymbolAddress((void**)&bhi, g_bhi);
    cudaGetSymbolAddress((void**)&blo, g_blo);
    cudaGetSymbolAddress((void**)&wh,  g_wthi);
    cudaGetSymbolAddress((void**)&wl,  g_wtlo);
    cudaGetSymbolAddress((void**)&rs,  g_rowsum);
    cudaGetSymbolAddress((void**)&rq,  g_rowsq);
    const size_t WSZ = (size_t)HD * HD;

    cudaFuncSetAttribute(gemm_mma3<0,1>, cudaFuncAttributeMaxDynamicSharedMemorySize, SMEM_TOTAL);
    cudaFuncSetAttribute(gemm_mma3<0,0>, cudaFuncAttributeMaxDynamicSharedMemorySize, SMEM_TOTAL);
    cudaFuncSetAttribute(gemm_mma1<0,1>, cudaFuncAttributeMaxDynamicSharedMemorySize, SMEM1_TOTAL);
    cudaFuncSetAttribute(gemm_mma1<1,0>, cudaFuncAttributeMaxDynamicSharedMemorySize, SMEM1_TOTAL);

    // ---- prep ----
    split_act<<<(NROWS * HD / 4) / 256, 256>>>((const float4*)x,
        (__nv_bfloat162*)ahi, (__nv_bfloat162*)alo);
    dim3 tb(32, 32), tg(HD / 32, HD / 32);
    wsplit_t<<<tg, tb>>>(W1, wh + 0 * WSZ, wl + 0 * WSZ);
    wsplit_t<<<tg, tb>>>(W2, wh + 1 * WSZ, wl + 1 * WSZ);
    wt_hi  <<<tg, tb>>>(W3, wh + 2 * WSZ);
    wt_hi  <<<tg, tb>>>(W4, wh + 3 * WSZ);
    cb_stats_kernel<<<HD, 256>>>(cb, rs, rq);

    dim3 gg(HD / BN, NROWS / BM);   // (8, 128)
    dim3 blk(THREADS);

    // encoder (3-term, high accuracy for VQ argmin)
    gemm_mma3<0,1><<<gg, blk, SMEM_TOTAL>>>(ahi, alo, wh + 0*WSZ, wl + 0*WSZ, b1,
                                            nullptr, bhi, blo);          // h1 (split)
    gemm_mma3<0,0><<<gg, blk, SMEM_TOTAL>>>(bhi, blo, wh + 1*WSZ, wl + 1*WSZ, b2,
                                            z_e, nullptr, nullptr);      // z_e fp32

    // VQ (writes z_q fp32 + bf16 into ahi)
    vq_kernel<<<NROWS, 256>>>(z_e, cb, rs, rq, z_q, ahi);

    // decoder (1-term bf16 — error diluted through sigmoid, within 1e-3 gate)
    gemm_mma1<0,1><<<gg, blk, SMEM1_TOTAL>>>(ahi, wh + 2*WSZ, b3,
                                             nullptr, bhi);              // h3 bf16
    gemm_mma1<1,0><<<gg, blk, SMEM1_TOTAL>>>(bhi, wh + 3*WSZ, b4,
                                             x_recon, nullptr);          // x_recon fp32
}

// round 7
// speedup vs baseline: 1.6879x; 1.0076x over previous
#include <cuda_runtime.h>
#include <cuda_bf16.h>
#include <math.h>
#include <stdint.h>

#define NROWS 32768
#define HD    1024

// ---------------------------------------------------------------------------
// Scratch (device globals; no allocations allowed)
// ---------------------------------------------------------------------------
__device__ __nv_bfloat16 g_ahi[(size_t)NROWS * HD];
__device__ __nv_bfloat16 g_alo[(size_t)NROWS * HD];
__device__ __nv_bfloat16 g_bhi[(size_t)NROWS * HD];
__device__ __nv_bfloat16 g_blo[(size_t)NROWS * HD];
__device__ __nv_bfloat16 g_wthi[4][(size_t)HD * HD];
__device__ __nv_bfloat16 g_wtlo[2][(size_t)HD * HD];   // lo only for W1, W2
__device__ float g_rowsum[HD];
__device__ float g_rowsq[HD];

// ---------------------------------------------------------------------------
// PTX helpers (sm_80-era only — harness PTX stage targets plain compute_103)
// ---------------------------------------------------------------------------
__device__ __forceinline__ uint32_t smem_to_u32(const void* p) {
    uint32_t a;
    asm("{ .reg .u64 t; cvta.to.shared.u64 t, %1; cvt.u32.u64 %0, t; }" : "=r"(a) : "l"(p));
    return a;
}
#define CP_ASYNC16(dst, src) \
    asm volatile("cp.async.cg.shared.global [%0], [%1], 16;" :: "r"(dst), "l"(src))
#define CP_COMMIT() asm volatile("cp.async.commit_group;" ::: "memory")
#define CP_WAIT2()  asm volatile("cp.async.wait_group 2;" ::: "memory")
#define CP_WAIT1()  asm volatile("cp.async.wait_group 1;" ::: "memory")
#define CP_WAIT0()  asm volatile("cp.async.wait_group 0;" ::: "memory")

#define LDSM4(r0, r1, r2, r3, addr) \
    asm volatile("ldmatrix.sync.aligned.m8n8.x4.shared.b16 {%0,%1,%2,%3}, [%4];" \
        : "=r"(r0), "=r"(r1), "=r"(r2), "=r"(r3) : "r"(addr))

#define MMA16816(d, a, b) \
    asm volatile("mma.sync.aligned.m16n8k16.row.col.f32.bf16.bf16.f32 " \
        "{%0,%1,%2,%3}, {%4,%5,%6,%7}, {%8,%9}, {%0,%1,%2,%3};" \
        : "+f"((d)[0]), "+f"((d)[1]), "+f"((d)[2]), "+f"((d)[3]) \
        : "r"((a)[0]), "r"((a)[1]), "r"((a)[2]), "r"((a)[3]), \
          "r"((b)[0]), "r"((b)[1]))

__device__ __forceinline__ void split1(float v, __nv_bfloat16& h, __nv_bfloat16& l) {
    h = __float2bfloat16(v);
    l = __float2bfloat16(v - __bfloat162float(h));
}

// ---------------------------------------------------------------------------
// Prep kernels
// ---------------------------------------------------------------------------
__global__ __launch_bounds__(256)
void split_act(const float4* __restrict__ x, __nv_bfloat162* __restrict__ hi,
               __nv_bfloat162* __restrict__ lo)
{
    size_t i = (size_t)blockIdx.x * 256 + threadIdx.x;
    float4 v = x[i];
    __nv_bfloat16 h0,l0,h1,l1,h2,l2,h3,l3;
    split1(v.x,h0,l0); split1(v.y,h1,l1); split1(v.z,h2,l2); split1(v.w,h3,l3);
    __nv_bfloat162 a,b;
    a.x=h0; a.y=h1; b.x=h2; b.y=h3;
    hi[2*i]=a; hi[2*i+1]=b;
    a.x=l0; a.y=l1; b.x=l2; b.y=l3;
    lo[2*i]=a; lo[2*i+1]=b;
}

__global__ __launch_bounds__(1024)
void wsplit_t(const float* __restrict__ W, __nv_bfloat16* __restrict__ hi,
              __nv_bfloat16* __restrict__ lo)
{
    __shared__ float s[32][33];
    int n0 = blockIdx.x * 32, k0 = blockIdx.y * 32;
    s[threadIdx.y][threadIdx.x] = W[(size_t)(k0 + threadIdx.y) * HD + n0 + threadIdx.x];
    __syncthreads();
    float v = s[threadIdx.x][threadIdx.y];
    int n = n0 + threadIdx.y, k = k0 + threadIdx.x;
    __nv_bfloat16 h, l; split1(v, h, l);
    hi[(size_t)n * HD + k] = h;
    lo[(size_t)n * HD + k] = l;
}

__global__ __launch_bounds__(1024)
void wt_hi(const float* __restrict__ W, __nv_bfloat16* __restrict__ hi)
{
    __shared__ float s[32][33];
    int n0 = blockIdx.x * 32, k0 = blockIdx.y * 32;
    s[threadIdx.y][threadIdx.x] = W[(size_t)(k0 + threadIdx.y) * HD + n0 + threadIdx.x];
    __syncthreads();
    float v = s[threadIdx.x][threadIdx.y];
    int n = n0 + threadIdx.y, k = k0 + threadIdx.x;
    hi[(size_t)n * HD + k] = __float2bfloat16(v);
}

__global__ __launch_bounds__(256)
void cb_stats_kernel(const float* __restrict__ cb, float* __restrict__ rowsum,
                     float* __restrict__ rowsq)
{
    const int i = blockIdx.x, tid = threadIdx.x;
    const float* row = cb + (size_t)i * HD;
    float s = 0.f, q = 0.f;
    for (int j = tid; j < HD; j += 256) { float v = row[j]; s += v; q = fmaf(v, v, q); }
    __shared__ float ss[256], qq[256];
    ss[tid] = s; qq[tid] = q;
    __syncthreads();
    for (int off = 128; off > 0; off >>= 1) {
        if (tid < off) { ss[tid] += ss[tid+off]; qq[tid] += qq[tid+off]; }
        __syncthreads();
    }
    if (tid == 0) { rowsum[i] = ss[0]; rowsq[i] = qq[0]; }
}

// ---------------------------------------------------------------------------
// VQ: argmin + gather (fp32 out + plain bf16 for decoder GEMM)
// ---------------------------------------------------------------------------
__global__ __launch_bounds__(256)
void vq_kernel(const float* __restrict__ ze, const float* __restrict__ cb,
               const float* __restrict__ rowsum, const float* __restrict__ rowsq,
               float* __restrict__ zq, __nv_bfloat16* __restrict__ zqh)
{
    const int n = blockIdx.x, tid = threadIdx.x;
    const float* z = ze + (size_t)n * HD;
    float best = INFINITY; int bidx = 0x7fffffff;
    #pragma unroll
    for (int j = 0; j < 4; j++) {
        int i = tid + j * 256;
        float zv = z[i];
        float d = fmaf(1024.0f * zv, zv, fmaf(-2.0f * zv, rowsum[i], rowsq[i]));
        if (d < best || (d == best && i < bidx)) { best = d; bidx = i; }
    }
    __shared__ float sd[256]; __shared__ int si[256];
    sd[tid] = best; si[tid] = bidx;
    __syncthreads();
    for (int off = 128; off > 0; off >>= 1) {
        if (tid < off) {
            float d2 = sd[tid+off]; int i2 = si[tid+off];
            if (d2 < sd[tid] || (d2 == sd[tid] && i2 < si[tid])) { sd[tid]=d2; si[tid]=i2; }
        }
        __syncthreads();
    }
    const int idx = si[0];
    float4 v = reinterpret_cast<const float4*>(cb + (size_t)idx * HD)[tid];
    reinterpret_cast<float4*>(zq + (size_t)n * HD)[tid] = v;
    __nv_bfloat162 a, b;
    a.x = __float2bfloat16(v.x); a.y = __float2bfloat16(v.y);
    b.x = __float2bfloat16(v.z); b.y = __float2bfloat16(v.w);
    __nv_bfloat162* ph = reinterpret_cast<__nv_bfloat162*>(zqh + (size_t)n * HD);
    ph[2*tid] = a; ph[2*tid+1] = b;
}

// ---------------------------------------------------------------------------
// GEMM geometry: CTA 256x128, 256 threads, 8 warps, warp tile 64x64,
// KC=64, cp.async pipeline, 128B-row xor swizzle.
// ---------------------------------------------------------------------------
#define BM 256
#define BN 128
#define KC 64
#define NKI (HD / KC)
#define THREADS 256

// ===== 3-term encoder: C = Ahi*Bhi + Ahi*Blo + Alo*Bhi =====
#define AHI_OFF 0
#define ALO_OFF 32768
#define BHI_OFF 65536
#define BLO_OFF 81920
#define STAGE_B 98304
#define SMEM_TOTAL (2 * STAGE_B)   // 196608

__device__ __forceinline__ void load_stage3(
    uint32_t sdst,
    const __nv_bfloat16* __restrict__ Ahi, const __nv_bfloat16* __restrict__ Alo,
    const __nv_bfloat16* __restrict__ Bhi, const __nv_bfloat16* __restrict__ Blo,
    int mbase, int nbase, int c, int tid)
{
    const int kel = c * KC;
    #pragma unroll
    for (int i = 0; i < 8; ++i) {
        int id = tid + i * THREADS;
        int row = id >> 3, u = id & 7;
        uint32_t so = row * 128 + ((u ^ (row & 7)) << 4);
        CP_ASYNC16(sdst + AHI_OFF + so,
                   (const char*)(Ahi + (size_t)(mbase + row) * HD + kel + u * 8));
        CP_ASYNC16(sdst + ALO_OFF + so,
                   (const char*)(Alo + (size_t)(mbase + row) * HD + kel + u * 8));
    }
    #pragma unroll
    for (int i = 0; i < 4; ++i) {
        int id = tid + i * THREADS;
        int row = id >> 3, u = id & 7;
        uint32_t so = row * 128 + ((u ^ (row & 7)) << 4);
        CP_ASYNC16(sdst + BHI_OFF + so,
                   (const char*)(Bhi + (size_t)(nbase + row) * HD + kel + u * 8));
        CP_ASYNC16(sdst + BLO_OFF + so,
                   (const char*)(Blo + (size_t)(nbase + row) * HD + kel + u * 8));
    }
}

// MODE: 0 = fp32 C; 1 = split bf16 Chi/Clo.
template<int MODE>
__global__ __launch_bounds__(THREADS, 1)
void gemm_mma3(const __nv_bfloat16* __restrict__ Ahi, const __nv_bfloat16* __restrict__ Alo,
               const __nv_bfloat16* __restrict__ Bhi, const __nv_bfloat16* __restrict__ Blo,
               const float* __restrict__ bias,
               float* __restrict__ Cf,
               __nv_bfloat16* __restrict__ Chi, __nv_bfloat16* __restrict__ Clo)
{
    extern __shared__ char smem[];
    const uint32_t sb = smem_to_u32(smem);
    const int tid  = threadIdx.x;
    const int wid  = tid >> 5;
    const int lane = tid & 31;
    const int wm = wid & 3;                 // 4 m-positions x 64
    const int wn = wid >> 2;                // 2 n-positions x 64
    const int mbase = blockIdx.y * BM;
    const int nbase = blockIdx.x * BN;

    float acc[4][8][4];
    #pragma unroll
    for (int i = 0; i < 4; i++)
        #pragma unroll
        for (int j = 0; j < 8; j++)
            #pragma unroll
            for (int k = 0; k < 4; k++) acc[i][j][k] = 0.f;

    const int a_row_l = lane & 15;
    const int a_half  = lane >> 4;
    const int b_n_l   = (lane & 7) + ((lane >> 4) << 3);
    const int b_half  = (lane >> 3) & 1;

    load_stage3(sb, Ahi, Alo, Bhi, Blo, mbase, nbase, 0, tid);
    CP_COMMIT();

    for (int c = 0; c < NKI; ++c) {
        if (c + 1 < NKI) {
            load_stage3(sb + ((c + 1) & 1) * STAGE_B, Ahi, Alo, Bhi, Blo,
                        mbase, nbase, c + 1, tid);
            CP_COMMIT();
            CP_WAIT1();
        } else {
            CP_WAIT0();
        }
        __syncthreads();

        const uint32_t st = sb + (c & 1) * STAGE_B;
        #pragma unroll
        for (int ks = 0; ks < 4; ++ks) {
            uint32_t ah[4][4], bh[8][2], bl[8][2];
            #pragma unroll
            for (int i = 0; i < 4; ++i) {
                int row = wm * 64 + i * 16 + a_row_l;
                int u = ks * 2 + a_half;
                LDSM4(ah[i][0], ah[i][1], ah[i][2], ah[i][3],
                      st + AHI_OFF + row * 128 + ((u ^ (row & 7)) << 4));
            }
            #pragma unroll
            for (int jj = 0; jj < 4; ++jj) {
                int n = wn * 64 + jj * 16 + b_n_l;
                int u = ks * 2 + b_half;
                LDSM4(bh[jj*2][0], bh[jj*2][1], bh[jj*2+1][0], bh[jj*2+1][1],
                      st + BHI_OFF + n * 128 + ((u ^ (n & 7)) << 4));
                LDSM4(bl[jj*2][0], bl[jj*2][1], bl[jj*2+1][0], bl[jj*2+1][1],
                      st + BLO_OFF + n * 128 + ((u ^ (n & 7)) << 4));
            }
            #pragma unroll
            for (int i = 0; i < 4; ++i)
                #pragma unroll
                for (int j = 0; j < 8; ++j) {
                    MMA16816(acc[i][j], ah[i], bh[j]);
                    MMA16816(acc[i][j], ah[i], bl[j]);
                }
            #pragma unroll
            for (int i = 0; i < 4; ++i) {
                int row = wm * 64 + i * 16 + a_row_l;
                int u = ks * 2 + a_half;
                LDSM4(ah[i][0], ah[i][1], ah[i][2], ah[i][3],
                      st + ALO_OFF + row * 128 + ((u ^ (row & 7)) << 4));
            }
            #pragma unroll
            for (int i = 0; i < 4; ++i)
                #pragma unroll
                for (int j = 0; j < 8; ++j)
                    MMA16816(acc[i][j], ah[i], bh[j]);
        }
        __syncthreads();
    }

    #pragma unroll
    for (int j = 0; j < 8; ++j) {
        const int col = nbase + wn * 64 + j * 8 + (lane & 3) * 2;
        const float2 bj = *reinterpret_cast<const float2*>(bias + col);
        #pragma unroll
        for (int i = 0; i < 4; ++i) {
            const int r0 = mbase + wm * 64 + i * 16 + (lane >> 2);
            const int r1 = r0 + 8;
            float v0 = fmaxf(acc[i][j][0] + bj.x, 0.f);
            float v1 = fmaxf(acc[i][j][1] + bj.y, 0.f);
            float v2 = fmaxf(acc[i][j][2] + bj.x, 0.f);
            float v3 = fmaxf(acc[i][j][3] + bj.y, 0.f);
            if (MODE == 0) {
                float2 p0 = {v0, v1}, p1 = {v2, v3};
                *reinterpret_cast<float2*>(Cf + (size_t)r0 * HD + col) = p0;
                *reinterpret_cast<float2*>(Cf + (size_t)r1 * HD + col) = p1;
            } else {
                __nv_bfloat16 h0,l0,h1,l1,h2,l2,h3,l3;
                split1(v0,h0,l0); split1(v1,h1,l1); split1(v2,h2,l2); split1(v3,h3,l3);
                __nv_bfloat162 hh0; hh0.x=h0; hh0.y=h1;
                __nv_bfloat162 ll0; ll0.x=l0; ll0.y=l1;
                __nv_bfloat162 hh1; hh1.x=h2; hh1.y=h3;
                __nv_bfloat162 ll1; ll1.x=l2; ll1.y=l3;
                *reinterpret_cast<__nv_bfloat162*>(Chi + (size_t)r0 * HD + col) = hh0;
                *reinterpret_cast<__nv_bfloat162*>(Clo + (size_t)r0 * HD + col) = ll0;
                *reinterpret_cast<__nv_bfloat162*>(Chi + (size_t)r1 * HD + col) = hh1;
                *reinterpret_cast<__nv_bfloat162*>(Clo + (size_t)r1 * HD + col) = ll1;
            }
        }
    }
}

// ===== 1-term decoder: C = act(A*B + bias) =====
#define A1_OFF 0
#define B1_OFF 32768
#define STAGE1_B 49152
#define SMEM1_TOTAL (3 * STAGE1_B)   // 147456

__device__ __forceinline__ void load_stage1(
    uint32_t sdst,
    const __nv_bfloat16* __restrict__ A, const __nv_bfloat16* __restrict__ B,
    int mbase, int nbase, int c, int tid)
{
    const int kel = c * KC;
    #pragma unroll
    for (int i = 0; i < 8; ++i) {
        int id = tid + i * THREADS;
        int row = id >> 3, u = id & 7;
        CP_ASYNC16(sdst + A1_OFF + row * 128 + ((u ^ (row & 7)) << 4),
                   (const char*)(A + (size_t)(mbase + row) * HD + kel + u * 8));
    }
    #pragma unroll
    for (int i = 0; i < 4; ++i) {
        int id = tid + i * THREADS;
        int row = id >> 3, u = id & 7;
        CP_ASYNC16(sdst + B1_OFF + row * 128 + ((u ^ (row & 7)) << 4),
                   (const char*)(B + (size_t)(nbase + row) * HD + kel + u * 8));
    }
}

// EPI: 0 = relu, 1 = sigmoid.  MODE: 0 = fp32 C; 1 = bf16 Chi only.
template<int EPI, int MODE>
__global__ __launch_bounds__(THREADS, 1)
void gemm_mma1(const __nv_bfloat16* __restrict__ A, const __nv_bfloat16* __restrict__ B,
               const float* __restrict__ bias,
               float* __restrict__ Cf, __nv_bfloat16* __restrict__ Chi)
{
    extern __shared__ char smem[];
    const uint32_t sb = smem_to_u32(smem);
    const int tid  = threadIdx.x;
    const int wid  = tid >> 5;
    const int lane = tid & 31;
    const int wm = wid & 3;
    const int wn = wid >> 2;
    const int mbase = blockIdx.y * BM;
    const int nbase = blockIdx.x * BN;

    float acc[4][8][4];
    #pragma unroll
    for (int i = 0; i < 4; i++)
        #pragma unroll
        for (int j = 0; j < 8; j++)
            #pragma unroll
            for (int k = 0; k < 4; k++) acc[i][j][k] = 0.f;

    const int a_row_l = lane & 15;
    const int a_half  = lane >> 4;
    const int b_n_l   = (lane & 7) + ((lane >> 4) << 3);
    const int b_half  = (lane >> 3) & 1;

    load_stage1(sb + 0 * STAGE1_B, A, B, mbase, nbase, 0, tid);
    CP_COMMIT();
    load_stage1(sb + 1 * STAGE1_B, A, B, mbase, nbase, 1, tid);
    CP_COMMIT();

    int buf = 0;
    for (int c = 0; c < NKI; ++c) {
        if (c + 2 < NKI) {
            int b2 = buf + 2; if (b2 >= 3) b2 -= 3;
            load_stage1(sb + b2 * STAGE1_B, A, B, mbase, nbase, c + 2, tid);
            CP_COMMIT();
            CP_WAIT2();
        } else if (c + 1 < NKI) {
            CP_WAIT1();
        } else {
            CP_WAIT0();
        }
        __syncthreads();

        const uint32_t st = sb + buf * STAGE1_B;
        #pragma unroll
        for (int ks = 0; ks < 4; ++ks) {
            uint32_t ah[4][4], bh[8][2];
            #pragma unroll
            for (int i = 0; i < 4; ++i) {
                int row = wm * 64 + i * 16 + a_row_l;
                int u = ks * 2 + a_half;
                LDSM4(ah[i][0], ah[i][1], ah[i][2], ah[i][3],
                      st + A1_OFF + row * 128 + ((u ^ (row & 7)) << 4));
            }
            #pragma unroll
            for (int jj = 0; jj < 4; ++jj) {
                int n = wn * 64 + jj * 16 + b_n_l;
                int u = ks * 2 + b_half;
                LDSM4(bh[jj*2][0], bh[jj*2][1], bh[jj*2+1][0], bh[jj*2+1][1],
                      st + B1_OFF + n * 128 + ((u ^ (n & 7)) << 4));
            }
            #pragma unroll
            for (int i = 0; i < 4; ++i)
                #pragma unroll
                for (int j = 0; j < 8; ++j)
                    MMA16816(acc[i][j], ah[i], bh[j]);
        }
        __syncthreads();
        buf = buf + 1; if (buf == 3) buf = 0;
    }

    #pragma unroll
    for (int j = 0; j < 8; ++j) {
        const int col = nbase + wn * 64 + j * 8 + (lane & 3) * 2;
        const float2 bj = *reinterpret_cast<const float2*>(bias + col);
        #pragma unroll
        for (int i = 0; i < 4; ++i) {
            const int r0 = mbase + wm * 64 + i * 16 + (lane >> 2);
            const int r1 = r0 + 8;
            float v0 = acc[i][j][0] + bj.x;
            float v1 = acc[i][j][1] + bj.y;
            float v2 = acc[i][j][2] + bj.x;
            float v3 = acc[i][j][3] + bj.y;
            if (EPI == 0) {
                v0 = fmaxf(v0, 0.f); v1 = fmaxf(v1, 0.f);
                v2 = fmaxf(v2, 0.f); v3 = fmaxf(v3, 0.f);
            } else {
                v0 = 1.f / (1.f + expf(-v0)); v1 = 1.f / (1.f + expf(-v1));
                v2 = 1.f / (1.f + expf(-v2)); v3 = 1.f / (1.f + expf(-v3));
            }
            if (MODE == 0) {
                float2 p0 = {v0, v1}, p1 = {v2, v3};
                *reinterpret_cast<float2*>(Cf + (size_t)r0 * HD + col) = p0;
                *reinterpret_cast<float2*>(Cf + (size_t)r1 * HD + col) = p1;
            } else {
                __nv_bfloat162 hh0, hh1;
                hh0.x = __float2bfloat16(v0); hh0.y = __float2bfloat16(v1);
                hh1.x = __float2bfloat16(v2); hh1.y = __float2bfloat16(v3);
                *reinterpret_cast<__nv_bfloat162*>(Chi + (size_t)r0 * HD + col) = hh0;
                *reinterpret_cast<__nv_bfloat162*>(Chi + (size_t)r1 * HD + col) = hh1;
            }
        }
    }
}

// ---------------------------------------------------------------------------
// Launch
// ---------------------------------------------------------------------------
extern "C" void kernel_launch(void* const* d_in, const int* in_sizes, int n_in,
                              void* d_out, int out_size)
{
    const float* x  = (const float*)d_in[0];
    const float* W1 = (const float*)d_in[1];
    const float* b1 = (const float*)d_in[2];
    const float* W2 = (const float*)d_in[3];
    const float* b2 = (const float*)d_in[4];
    const float* cb = (const float*)d_in[5];
    const float* W3 = (const float*)d_in[6];
    const float* b3 = (const float*)d_in[7];
    const float* W4 = (const float*)d_in[8];
    const float* b4 = (const float*)d_in[9];

    float* out = (float*)d_out;
    float* x_recon = out;
    float* z_e = out + (size_t)NROWS * HD;
    float* z_q = z_e + (size_t)NROWS * HD;

    __nv_bfloat16 *ahi, *alo, *bhi, *blo, *wh, *wl;
    float *rs, *rq;
    cudaGetSymbolAddress((void**)&ahi, g_ahi);
    cudaGetSymbolAddress((void**)&alo, g_alo);
    cudaGetSymbolAddress((void**)&bhi, g_bhi);
    cudaGetSymbolAddress((void**)&blo, g_blo);
    cudaGetSymbolAddress((void**)&wh,  g_wthi);
    cudaGetSymbolAddress((void**)&wl,  g_wtlo);
    cudaGetSymbolAddress((void**)&rs,  g_rowsum);
    cudaGetSymbolAddress((void**)&rq,  g_rowsq);
    const size_t WSZ = (size_t)HD * HD;

    cudaFuncSetAttribute(gemm_mma3<1>,   cudaFuncAttributeMaxDynamicSharedMemorySize, SMEM_TOTAL);
    cudaFuncSetAttribute(gemm_mma3<0>,   cudaFuncAttributeMaxDynamicSharedMemorySize, SMEM_TOTAL);
    cudaFuncSetAttribute(gemm_mma1<0,1>, cudaFuncAttributeMaxDynamicSharedMemorySize, SMEM1_TOTAL);
    cudaFuncSetAttribute(gemm_mma1<1,0>, cudaFuncAttributeMaxDynamicSharedMemorySize, SMEM1_TOTAL);

    // ---- prep ----
    split_act<<<(NROWS * HD / 4) / 256, 256>>>((const float4*)x,
        (__nv_bfloat162*)ahi, (__nv_bfloat162*)alo);
    dim3 tb(32, 32), tg(HD / 32, HD / 32);
    wsplit_t<<<tg, tb>>>(W1, wh + 0 * WSZ, wl + 0 * WSZ);
    wsplit_t<<<tg, tb>>>(W2, wh + 1 * WSZ, wl + 1 * WSZ);
    wt_hi  <<<tg, tb>>>(W3, wh + 2 * WSZ);
    wt_hi  <<<tg, tb>>>(W4, wh + 3 * WSZ);
    cb_stats_kernel<<<HD, 256>>>(cb, rs, rq);

    dim3 gg(HD / BN, NROWS / BM);   // (8, 128)
    dim3 blk(THREADS);

    // encoder (3-term, high accuracy for VQ argmin + z_e output)
    gemm_mma3<1><<<gg, blk, SMEM_TOTAL>>>(ahi, alo, wh + 0*WSZ, wl + 0*WSZ, b1,
                                          nullptr, bhi, blo);            // h1 (split)
    gemm_mma3<0><<<gg, blk, SMEM_TOTAL>>>(bhi, blo, wh + 1*WSZ, wl + 1*WSZ, b2,
                                          z_e, nullptr, nullptr);        // z_e fp32

    // VQ (writes z_q fp32 + bf16 into ahi)
    vq_kernel<<<NROWS, 256>>>(z_e, cb, rs, rq, z_q, ahi);

    // decoder (1-term bf16)
    gemm_mma1<0,1><<<gg, blk, SMEM1_TOTAL>>>(ahi, wh + 2*WSZ, b3, nullptr, bhi);
    gemm_mma1<1,0><<<gg, blk, SMEM1_TOTAL>>>(bhi, wh + 3*WSZ, b4, x_recon, nullptr);
}

// round 8
// speedup vs baseline: 1.6883x; 1.0002x over previous
#include <cuda_runtime.h>
#include <cuda_bf16.h>
#include <math.h>
#include <stdint.h>

#define NROWS 32768
#define HD    1024

// ---------------------------------------------------------------------------
// Scratch (device globals; no allocations allowed)
// ---------------------------------------------------------------------------
__device__ __nv_bfloat16 g_ahi[(size_t)NROWS * HD];
__device__ __nv_bfloat16 g_alo[(size_t)NROWS * HD];
__device__ __nv_bfloat16 g_bhi[(size_t)NROWS * HD];
__device__ __nv_bfloat16 g_blo[(size_t)NROWS * HD];
__device__ __nv_bfloat16 g_wthi[4][(size_t)HD * HD];
__device__ __nv_bfloat16 g_wtlo[2][(size_t)HD * HD];   // lo only for W1, W2
__device__ float g_rowsum[HD];
__device__ float g_rowsq[HD];

// ---------------------------------------------------------------------------
// PTX helpers (sm_80-era only — harness PTX stage targets plain compute_103)
// ---------------------------------------------------------------------------
__device__ __forceinline__ uint32_t smem_to_u32(const void* p) {
    uint32_t a;
    asm("{ .reg .u64 t; cvta.to.shared.u64 t, %1; cvt.u32.u64 %0, t; }" : "=r"(a) : "l"(p));
    return a;
}
#define CP_ASYNC16(dst, src) \
    asm volatile("cp.async.cg.shared.global [%0], [%1], 16;" :: "r"(dst), "l"(src))
#define CP_COMMIT() asm volatile("cp.async.commit_group;" ::: "memory")
#define CP_WAIT2()  asm volatile("cp.async.wait_group 2;" ::: "memory")
#define CP_WAIT1()  asm volatile("cp.async.wait_group 1;" ::: "memory")
#define CP_WAIT0()  asm volatile("cp.async.wait_group 0;" ::: "memory")

#define LDSM4(r0, r1, r2, r3, addr) \
    asm volatile("ldmatrix.sync.aligned.m8n8.x4.shared.b16 {%0,%1,%2,%3}, [%4];" \
        : "=r"(r0), "=r"(r1), "=r"(r2), "=r"(r3) : "r"(addr))

#define MMA16816(d, a, b) \
    asm volatile("mma.sync.aligned.m16n8k16.row.col.f32.bf16.bf16.f32 " \
        "{%0,%1,%2,%3}, {%4,%5,%6,%7}, {%8,%9}, {%0,%1,%2,%3};" \
        : "+f"((d)[0]), "+f"((d)[1]), "+f"((d)[2]), "+f"((d)[3]) \
        : "r"((a)[0]), "r"((a)[1]), "r"((a)[2]), "r"((a)[3]), \
          "r"((b)[0]), "r"((b)[1]))

__device__ __forceinline__ void split1(float v, __nv_bfloat16& h, __nv_bfloat16& l) {
    h = __float2bfloat16(v);
    l = __float2bfloat16(v - __bfloat162float(h));
}

// ---------------------------------------------------------------------------
// Prep kernels
// ---------------------------------------------------------------------------
__global__ __launch_bounds__(256)
void split_act(const float4* __restrict__ x, __nv_bfloat162* __restrict__ hi,
               __nv_bfloat162* __restrict__ lo)
{
    size_t i = (size_t)blockIdx.x * 256 + threadIdx.x;
    float4 v = x[i];
    __nv_bfloat16 h0,l0,h1,l1,h2,l2,h3,l3;
    split1(v.x,h0,l0); split1(v.y,h1,l1); split1(v.z,h2,l2); split1(v.w,h3,l3);
    __nv_bfloat162 a,b;
    a.x=h0; a.y=h1; b.x=h2; b.y=h3;
    hi[2*i]=a; hi[2*i+1]=b;
    a.x=l0; a.y=l1; b.x=l2; b.y=l3;
    lo[2*i]=a; lo[2*i+1]=b;
}

__global__ __launch_bounds__(1024)
void wsplit_t(const float* __restrict__ W, __nv_bfloat16* __restrict__ hi,
              __nv_bfloat16* __restrict__ lo)
{
    __shared__ float s[32][33];
    int n0 = blockIdx.x * 32, k0 = blockIdx.y * 32;
    s[threadIdx.y][threadIdx.x] = W[(size_t)(k0 + threadIdx.y) * HD + n0 + threadIdx.x];
    __syncthreads();
    float v = s[threadIdx.x][threadIdx.y];
    int n = n0 + threadIdx.y, k = k0 + threadIdx.x;
    __nv_bfloat16 h, l; split1(v, h, l);
    hi[(size_t)n * HD + k] = h;
    lo[(size_t)n * HD + k] = l;
}

__global__ __launch_bounds__(1024)
void wt_hi(const float* __restrict__ W, __nv_bfloat16* __restrict__ hi)
{
    __shared__ float s[32][33];
    int n0 = blockIdx.x * 32, k0 = blockIdx.y * 32;
    s[threadIdx.y][threadIdx.x] = W[(size_t)(k0 + threadIdx.y) * HD + n0 + threadIdx.x];
    __syncthreads();
    float v = s[threadIdx.x][threadIdx.y];
    int n = n0 + threadIdx.y, k = k0 + threadIdx.x;
    hi[(size_t)n * HD + k] = __float2bfloat16(v);
}

__global__ __launch_bounds__(256)
void cb_stats_kernel(const float* __restrict__ cb, float* __restrict__ rowsum,
                     float* __restrict__ rowsq)
{
    const int i = blockIdx.x, tid = threadIdx.x;
    const float* row = cb + (size_t)i * HD;
    float s = 0.f, q = 0.f;
    for (int j = tid; j < HD; j += 256) { float v = row[j]; s += v; q = fmaf(v, v, q); }
    __shared__ float ss[256], qq[256];
    ss[tid] = s; qq[tid] = q;
    __syncthreads();
    for (int off = 128; off > 0; off >>= 1) {
        if (tid < off) { ss[tid] += ss[tid+off]; qq[tid] += qq[tid+off]; }
        __syncthreads();
    }
    if (tid == 0) { rowsum[i] = ss[0]; rowsq[i] = qq[0]; }
}

// ---------------------------------------------------------------------------
// VQ: argmin + gather (fp32 out + plain bf16 for decoder GEMM)
// ---------------------------------------------------------------------------
__global__ __launch_bounds__(256)
void vq_kernel(const float* __restrict__ ze, const float* __restrict__ cb,
               const float* __restrict__ rowsum, const float* __restrict__ rowsq,
               float* __restrict__ zq, __nv_bfloat16* __restrict__ zqh)
{
    const int n = blockIdx.x, tid = threadIdx.x;
    const float* z = ze + (size_t)n * HD;
    float best = INFINITY; int bidx = 0x7fffffff;
    #pragma unroll
    for (int j = 0; j < 4; j++) {
        int i = tid + j * 256;
        float zv = z[i];
        float d = fmaf(1024.0f * zv, zv, fmaf(-2.0f * zv, rowsum[i], rowsq[i]));
        if (d < best || (d == best && i < bidx)) { best = d; bidx = i; }
    }
    __shared__ float sd[256]; __shared__ int si[256];
    sd[tid] = best; si[tid] = bidx;
    __syncthreads();
    for (int off = 128; off > 0; off >>= 1) {
        if (tid < off) {
            float d2 = sd[tid+off]; int i2 = si[tid+off];
            if (d2 < sd[tid] || (d2 == sd[tid] && i2 < si[tid])) { sd[tid]=d2; si[tid]=i2; }
        }
        __syncthreads();
    }
    const int idx = si[0];
    float4 v = reinterpret_cast<const float4*>(cb + (size_t)idx * HD)[tid];
    reinterpret_cast<float4*>(zq + (size_t)n * HD)[tid] = v;
    __nv_bfloat162 a, b;
    a.x = __float2bfloat16(v.x); a.y = __float2bfloat16(v.y);
    b.x = __float2bfloat16(v.z); b.y = __float2bfloat16(v.w);
    __nv_bfloat162* ph = reinterpret_cast<__nv_bfloat162*>(zqh + (size_t)n * HD);
    ph[2*tid] = a; ph[2*tid+1] = b;
}

// ---------------------------------------------------------------------------
// GEMM geometry: CTA 256x128, 256 threads, 8 warps, warp tile 64x64,
// KC=64, cp.async pipeline, 128B-row xor swizzle.
// ---------------------------------------------------------------------------
#define BM 256
#define BN 128
#define KC 64
#define NKI (HD / KC)
#define THREADS 256

// ===== 3-term encoder: C = Ahi*Bhi + Ahi*Blo + Alo*Bhi =====
#define AHI_OFF 0
#define ALO_OFF 32768
#define BHI_OFF 65536
#define BLO_OFF 81920
#define STAGE_B 98304
#define SMEM_TOTAL (2 * STAGE_B)   // 196608

__device__ __forceinline__ void load_stage3(
    uint32_t sdst,
    const __nv_bfloat16* __restrict__ Ahi, const __nv_bfloat16* __restrict__ Alo,
    const __nv_bfloat16* __restrict__ Bhi, const __nv_bfloat16* __restrict__ Blo,
    int mbase, int nbase, int c, int tid)
{
    const int kel = c * KC;
    #pragma unroll
    for (int i = 0; i < 8; ++i) {
        int id = tid + i * THREADS;
        int row = id >> 3, u = id & 7;
        uint32_t so = row * 128 + ((u ^ (row & 7)) << 4);
        CP_ASYNC16(sdst + AHI_OFF + so,
                   (const char*)(Ahi + (size_t)(mbase + row) * HD + kel + u * 8));
        CP_ASYNC16(sdst + ALO_OFF + so,
                   (const char*)(Alo + (size_t)(mbase + row) * HD + kel + u * 8));
    }
    #pragma unroll
    for (int i = 0; i < 4; ++i) {
        int id = tid + i * THREADS;
        int row = id >> 3, u = id & 7;
        uint32_t so = row * 128 + ((u ^ (row & 7)) << 4);
        CP_ASYNC16(sdst + BHI_OFF + so,
                   (const char*)(Bhi + (size_t)(nbase + row) * HD + kel + u * 8));
        CP_ASYNC16(sdst + BLO_OFF + so,
                   (const char*)(Blo + (size_t)(nbase + row) * HD + kel + u * 8));
    }
}

// MODE: 0 = fp32 C; 1 = split bf16 Chi/Clo.
template<int MODE>
__global__ __launch_bounds__(THREADS, 1)
void gemm_mma3(const __nv_bfloat16* __restrict__ Ahi, const __nv_bfloat16* __restrict__ Alo,
               const __nv_bfloat16* __restrict__ Bhi, const __nv_bfloat16* __restrict__ Blo,
               const float* __restrict__ bias,
               float* __restrict__ Cf,
               __nv_bfloat16* __restrict__ Chi, __nv_bfloat16* __restrict__ Clo)
{
    extern __shared__ char smem[];
    const uint32_t sb = smem_to_u32(smem);
    const int tid  = threadIdx.x;
    const int wid  = tid >> 5;
    const int lane = tid & 31;
    const int wm = wid & 3;                 // 4 m-positions x 64
    const int wn = wid >> 2;                // 2 n-positions x 64
    const int mbase = blockIdx.y * BM;
    const int nbase = blockIdx.x * BN;

    float acc[4][8][4];
    #pragma unroll
    for (int i = 0; i < 4; i++)
        #pragma unroll
        for (int j = 0; j < 8; j++)
            #pragma unroll
            for (int k = 0; k < 4; k++) acc[i][j][k] = 0.f;

    const int a_row_l = lane & 15;
    const int a_half  = lane >> 4;
    const int b_n_l   = (lane & 7) + ((lane >> 4) << 3);
    const int b_half  = (lane >> 3) & 1;

    load_stage3(sb, Ahi, Alo, Bhi, Blo, mbase, nbase, 0, tid);
    CP_COMMIT();

    for (int c = 0; c < NKI; ++c) {
        if (c + 1 < NKI) {
            load_stage3(sb + ((c + 1) & 1) * STAGE_B, Ahi, Alo, Bhi, Blo,
                        mbase, nbase, c + 1, tid);
            CP_COMMIT();
            CP_WAIT1();
        } else {
            CP_WAIT0();
        }
        __syncthreads();

        const uint32_t st = sb + (c & 1) * STAGE_B;
        #pragma unroll
        for (int ks = 0; ks < 4; ++ks) {
            uint32_t ah[4][4], bh[8][2], bl[8][2];
            #pragma unroll
            for (int i = 0; i < 4; ++i) {
                int row = wm * 64 + i * 16 + a_row_l;
                int u = ks * 2 + a_half;
                LDSM4(ah[i][0], ah[i][1], ah[i][2], ah[i][3],
                      st + AHI_OFF + row * 128 + ((u ^ (row & 7)) << 4));
            }
            #pragma unroll
            for (int jj = 0; jj < 4; ++jj) {
                int n = wn * 64 + jj * 16 + b_n_l;
                int u = ks * 2 + b_half;
                LDSM4(bh[jj*2][0], bh[jj*2][1], bh[jj*2+1][0], bh[jj*2+1][1],
                      st + BHI_OFF + n * 128 + ((u ^ (n & 7)) << 4));
                LDSM4(bl[jj*2][0], bl[jj*2][1], bl[jj*2+1][0], bl[jj*2+1][1],
                      st + BLO_OFF + n * 128 + ((u ^ (n & 7)) << 4));
            }
            #pragma unroll
            for (int i = 0; i < 4; ++i)
                #pragma unroll
                for (int j = 0; j < 8; ++j) {
                    MMA16816(acc[i][j], ah[i], bh[j]);
                    MMA16816(acc[i][j], ah[i], bl[j]);
                }
            #pragma unroll
            for (int i = 0; i < 4; ++i) {
                int row = wm * 64 + i * 16 + a_row_l;
                int u = ks * 2 + a_half;
                LDSM4(ah[i][0], ah[i][1], ah[i][2], ah[i][3],
                      st + ALO_OFF + row * 128 + ((u ^ (row & 7)) << 4));
            }
            #pragma unroll
            for (int i = 0; i < 4; ++i)
                #pragma unroll
                for (int j = 0; j < 8; ++j)
                    MMA16816(acc[i][j], ah[i], bh[j]);
        }
        __syncthreads();
    }

    #pragma unroll
    for (int j = 0; j < 8; ++j) {
        const int col = nbase + wn * 64 + j * 8 + (lane & 3) * 2;
        const float2 bj = *reinterpret_cast<const float2*>(bias + col);
        #pragma unroll
        for (int i = 0; i < 4; ++i) {
            const int r0 = mbase + wm * 64 + i * 16 + (lane >> 2);
            const int r1 = r0 + 8;
            float v0 = fmaxf(acc[i][j][0] + bj.x, 0.f);
            float v1 = fmaxf(acc[i][j][1] + bj.y, 0.f);
            float v2 = fmaxf(acc[i][j][2] + bj.x, 0.f);
            float v3 = fmaxf(acc[i][j][3] + bj.y, 0.f);
            if (MODE == 0) {
                float2 p0 = {v0, v1}, p1 = {v2, v3};
                *reinterpret_cast<float2*>(Cf + (size_t)r0 * HD + col) = p0;
                *reinterpret_cast<float2*>(Cf + (size_t)r1 * HD + col) = p1;
            } else {
                __nv_bfloat16 h0,l0,h1,l1,h2,l2,h3,l3;
                split1(v0,h0,l0); split1(v1,h1,l1); split1(v2,h2,l2); split1(v3,h3,l3);
                __nv_bfloat162 hh0; hh0.x=h0; hh0.y=h1;
                __nv_bfloat162 ll0; ll0.x=l0; ll0.y=l1;
                __nv_bfloat162 hh1; hh1.x=h2; hh1.y=h3;
                __nv_bfloat162 ll1; ll1.x=l2; ll1.y=l3;
                *reinterpret_cast<__nv_bfloat162*>(Chi + (size_t)r0 * HD + col) = hh0;
                *reinterpret_cast<__nv_bfloat162*>(Clo + (size_t)r0 * HD + col) = ll0;
                *reinterpret_cast<__nv_bfloat162*>(Chi + (size_t)r1 * HD + col) = hh1;
                *reinterpret_cast<__nv_bfloat162*>(Clo + (size_t)r1 * HD + col) = ll1;
            }
        }
    }
}

// ===== 1-term decoder: C = act(A*B + bias) =====
#define A1_OFF 0
#define B1_OFF 32768
#define STAGE1_B 49152
#define SMEM1_TOTAL (3 * STAGE1_B)   // 147456

__device__ __forceinline__ void load_stage1(
    uint32_t sdst,
    const __nv_bfloat16* __restrict__ A, const __nv_bfloat16* __restrict__ B,
    int mbase, int nbase, int c, int tid)
{
    const int kel = c * KC;
    #pragma unroll
    for (int i = 0; i < 8; ++i) {
        int id = tid + i * THREADS;
        int row = id >> 3, u = id & 7;
        CP_ASYNC16(sdst + A1_OFF + row * 128 + ((u ^ (row & 7)) << 4),
                   (const char*)(A + (size_t)(mbase + row) * HD + kel + u * 8));
    }
    #pragma unroll
    for (int i = 0; i < 4; ++i) {
        int id = tid + i * THREADS;
        int row = id >> 3, u = id & 7;
        CP_ASYNC16(sdst + B1_OFF + row * 128 + ((u ^ (row & 7)) << 4),
                   (const char*)(B + (size_t)(nbase + row) * HD + kel + u * 8));
    }
}

// EPI: 0 = relu, 1 = sigmoid.  MODE: 0 = fp32 C; 1 = bf16 Chi only.
template<int EPI, int MODE>
__global__ __launch_bounds__(THREADS, 1)
void gemm_mma1(const __nv_bfloat16* __restrict__ A, const __nv_bfloat16* __restrict__ B,
               const float* __restrict__ bias,
               float* __restrict__ Cf, __nv_bfloat16* __restrict__ Chi)
{
    extern __shared__ char smem[];
    const uint32_t sb = smem_to_u32(smem);
    const int tid  = threadIdx.x;
    const int wid  = tid >> 5;
    const int lane = tid & 31;
    const int wm = wid & 3;
    const int wn = wid >> 2;
    const int mbase = blockIdx.y * BM;
    const int nbase = blockIdx.x * BN;

    float acc[4][8][4];
    #pragma unroll
    for (int i = 0; i < 4; i++)
        #pragma unroll
        for (int j = 0; j < 8; j++)
            #pragma unroll
            for (int k = 0; k < 4; k++) acc[i][j][k] = 0.f;

    const int a_row_l = lane & 15;
    const int a_half  = lane >> 4;
    const int b_n_l   = (lane & 7) + ((lane >> 4) << 3);
    const int b_half  = (lane >> 3) & 1;

    load_stage1(sb + 0 * STAGE1_B, A, B, mbase, nbase, 0, tid);
    CP_COMMIT();
    load_stage1(sb + 1 * STAGE1_B, A, B, mbase, nbase, 1, tid);
    CP_COMMIT();

    int buf = 0;
    for (int c = 0; c < NKI; ++c) {
        if (c + 2 < NKI) {
            int b2 = buf + 2; if (b2 >= 3) b2 -= 3;
            load_stage1(sb + b2 * STAGE1_B, A, B, mbase, nbase, c + 2, tid);
            CP_COMMIT();
            CP_WAIT2();
        } else if (c + 1 < NKI) {
            CP_WAIT1();
        } else {
            CP_WAIT0();
        }
        __syncthreads();

        const uint32_t st = sb + buf * STAGE1_B;
        #pragma unroll
        for (int ks = 0; ks < 4; ++ks) {
            uint32_t ah[4][4], bh[8][2];
            #pragma unroll
            for (int i = 0; i < 4; ++i) {
                int row = wm * 64 + i * 16 + a_row_l;
                int u = ks * 2 + a_half;
                LDSM4(ah[i][0], ah[i][1], ah[i][2], ah[i][3],
                      st + A1_OFF + row * 128 + ((u ^ (row & 7)) << 4));
            }
            #pragma unroll
            for (int jj = 0; jj < 4; ++jj) {
                int n = wn * 64 + jj * 16 + b_n_l;
                int u = ks * 2 + b_half;
                LDSM4(bh[jj*2][0], bh[jj*2][1], bh[jj*2+1][0], bh[jj*2+1][1],
                      st + B1_OFF + n * 128 + ((u ^ (n & 7)) << 4));
            }
            #pragma unroll
            for (int i = 0; i < 4; ++i)
                #pragma unroll
                for (int j = 0; j < 8; ++j)
                    MMA16816(acc[i][j], ah[i], bh[j]);
        }
        __syncthreads();
        buf = buf + 1; if (buf == 3) buf = 0;
    }

    #pragma unroll
    for (int j = 0; j < 8; ++j) {
        const int col = nbase + wn * 64 + j * 8 + (lane & 3) * 2;
        const float2 bj = *reinterpret_cast<const float2*>(bias + col);
        #pragma unroll
        for (int i = 0; i < 4; ++i) {
            const int r0 = mbase + wm * 64 + i * 16 + (lane >> 2);
            const int r1 = r0 + 8;
            float v0 = acc[i][j][0] + bj.x;
            float v1 = acc[i][j][1] + bj.y;
            float v2 = acc[i][j][2] + bj.x;
            float v3 = acc[i][j][3] + bj.y;
            if (EPI == 0) {
                v0 = fmaxf(v0, 0.f); v1 = fmaxf(v1, 0.f);
                v2 = fmaxf(v2, 0.f); v3 = fmaxf(v3, 0.f);
            } else {
                v0 = 1.f / (1.f + expf(-v0)); v1 = 1.f / (1.f + expf(-v1));
                v2 = 1.f / (1.f + expf(-v2)); v3 = 1.f / (1.f + expf(-v3));
            }
            if (MODE == 0) {
                float2 p0 = {v0, v1}, p1 = {v2, v3};
                *reinterpret_cast<float2*>(Cf + (size_t)r0 * HD + col) = p0;
                *reinterpret_cast<float2*>(Cf + (size_t)r1 * HD + col) = p1;
            } else {
                __nv_bfloat162 hh0, hh1;
                hh0.x = __float2bfloat16(v0); hh0.y = __float2bfloat16(v1);
                hh1.x = __float2bfloat16(v2); hh1.y = __float2bfloat16(v3);
                *reinterpret_cast<__nv_bfloat162*>(Chi + (size_t)r0 * HD + col) = hh0;
                *reinterpret_cast<__nv_bfloat162*>(Chi + (size_t)r1 * HD + col) = hh1;
            }
        }
    }
}

// ---------------------------------------------------------------------------
// Launch
// ---------------------------------------------------------------------------
extern "C" void kernel_launch(void* const* d_in, const int* in_sizes, int n_in,
                              void* d_out, int out_size)
{
    const float* x  = (const float*)d_in[0];
    const float* W1 = (const float*)d_in[1];
    const float* b1 = (const float*)d_in[2];
    const float* W2 = (const float*)d_in[3];
    const float* b2 = (const float*)d_in[4];
    const float* cb = (const float*)d_in[5];
    const float* W3 = (const float*)d_in[6];
    const float* b3 = (const float*)d_in[7];
    const float* W4 = (const float*)d_in[8];
    const float* b4 = (const float*)d_in[9];

    float* out = (float*)d_out;
    float* x_recon = out;
    float* z_e = out + (size_t)NROWS * HD;
    float* z_q = z_e + (size_t)NROWS * HD;

    __nv_bfloat16 *ahi, *alo, *bhi, *blo, *wh, *wl;
    float *rs, *rq;
    cudaGetSymbolAddress((void**)&ahi, g_ahi);
    cudaGetSymbolAddress((void**)&alo, g_alo);
    cudaGetSymbolAddress((void**)&bhi, g_bhi);
    cudaGetSymbolAddress((void**)&blo, g_blo);
    cudaGetSymbolAddress((void**)&wh,  g_wthi);
    cudaGetSymbolAddress((void**)&wl,  g_wtlo);
    cudaGetSymbolAddress((void**)&rs,  g_rowsum);
    cudaGetSymbolAddress((void**)&rq,  g_rowsq);
    const size_t WSZ = (size_t)HD * HD;

    cudaFuncSetAttribute(gemm_mma3<1>,   cudaFuncAttributeMaxDynamicSharedMemorySize, SMEM_TOTAL);
    cudaFuncSetAttribute(gemm_mma3<0>,   cudaFuncAttributeMaxDynamicSharedMemorySize, SMEM_TOTAL);
    cudaFuncSetAttribute(gemm_mma1<0,1>, cudaFuncAttributeMaxDynamicSharedMemorySize, SMEM1_TOTAL);
    cudaFuncSetAttribute(gemm_mma1<1,0>, cudaFuncAttributeMaxDynamicSharedMemorySize, SMEM1_TOTAL);

    // ---- prep ----
    split_act<<<(NROWS * HD / 4) / 256, 256>>>((const float4*)x,
        (__nv_bfloat162*)ahi, (__nv_bfloat162*)alo);
    dim3 tb(32, 32), tg(HD / 32, HD / 32);
    wsplit_t<<<tg, tb>>>(W1, wh + 0 * WSZ, wl + 0 * WSZ);
    wsplit_t<<<tg, tb>>>(W2, wh + 1 * WSZ, wl + 1 * WSZ);
    wt_hi  <<<tg, tb>>>(W3, wh + 2 * WSZ);
    wt_hi  <<<tg, tb>>>(W4, wh + 3 * WSZ);
    cb_stats_kernel<<<HD, 256>>>(cb, rs, rq);

    dim3 gg(HD / BN, NROWS / BM);   // (8, 128)
    dim3 blk(THREADS);

    // encoder (3-term, high accuracy for VQ argmin + z_e output)
    gemm_mma3<1><<<gg, blk, SMEM_TOTAL>>>(ahi, alo, wh + 0*WSZ, wl + 0*WSZ, b1,
                                          nullptr, bhi, blo);            // h1 (split)
    gemm_mma3<0><<<gg, blk, SMEM_TOTAL>>>(bhi, blo, wh + 1*WSZ, wl + 1*WSZ, b2,
                                          z_e, nullptr, nullptr);        // z_e fp32

    // VQ (writes z_q fp32 + bf16 into ahi)
    vq_kernel<<<NROWS, 256>>>(z_e, cb, rs, rq, z_q, ahi);

    // decoder (1-term bf16)
    gemm_mma1<0,1><<<gg, blk, SMEM1_TOTAL>>>(ahi, wh + 2*WSZ, b3, nullptr, bhi);
    gemm_mma1<1,0><<<gg, blk, SMEM1_TOTAL>>>(bhi, wh + 3*WSZ, b4, x_recon, nullptr);
}